// round 2
// baseline (speedup 1.0000x reference)
#include <cuda_runtime.h>
#include <math.h>

#define B_SZ   32
#define NC     62
#define F_     256
#define NE     512
#define NCF    15872          // NC*F_
#define MROWS  1984           // B_SZ*NC
#define ZROWS  123008         // B_SZ*NC*NC
#define GSIZE  31490048       // MROWS*NCF == ZROWS*F_

// ---- scratch (static device globals: no allocation allowed) ----
__device__ float d_o[MROWS * F_];
__device__ float d_oq[MROWS * F_];
__device__ float d_g[GSIZE];          // g, then z in-place
__device__ float d_cbT[F_ * NE];      // codebook transposed [c][k]
__device__ float d_cbnorm[NE];
__device__ int   d_idx[ZROWS];
__device__ int   d_histb[B_SZ * NE];
__device__ float d_sfac[B_SZ * F_];   // 1 + sigmoid(...)
__device__ float d_T[B_SZ * NE];      // lookup: sum_c elu(cb[k,c]*sfac[b,c])
__device__ float d_loss;

__device__ __forceinline__ float elu1(float x) {
    return x > 0.f ? x : (expf(x) - 1.f);
}

// ---- zero per-call state ----
__global__ void init_kernel() {
    int t = threadIdx.x;
    for (int i = t; i < B_SZ * NE; i += blockDim.x) d_histb[i] = 0;
    if (t == 0) d_loss = 0.f;
}

// ---- codebook transpose + squared norms ----
__global__ __launch_bounds__(256) void cbprep_kernel(const float* __restrict__ cb) {
    int k = blockIdx.x, c = threadIdx.x;
    float v = cb[k * F_ + c];
    d_cbT[c * NE + k] = v;
    __shared__ float red[256];
    red[c] = v * v;
    __syncthreads();
    for (int s = 128; s > 0; s >>= 1) {
        if (c < s) red[c] += red[c + s];
        __syncthreads();
    }
    if (c == 0) d_cbnorm[k] = red[0];
}

// ---- o = p @ x + bias ----
__global__ __launch_bounds__(256) void a1_kernel(const float* __restrict__ p,
                                                 const float* __restrict__ x,
                                                 const float* __restrict__ bias) {
    int row = blockIdx.x;           // b*NC + i
    int b = row / NC, i = row - b * NC;
    int c = threadIdx.x;
    __shared__ float sp[NC];
    if (c < NC) sp[c] = p[i * NC + c];
    __syncthreads();
    float acc = bias[i * F_ + c];
    const float* xb = x + (size_t)b * NC * F_ + c;
#pragma unroll 1
    for (int j = 0; j < NC; j++) acc += sp[j] * xb[j * F_];
    d_o[row * F_ + c] = acc;
}

// ---- oq = o @ q ----
__global__ __launch_bounds__(256) void a2_kernel(const float* __restrict__ q) {
    int row = blockIdx.x;
    int c = threadIdx.x;
    __shared__ float so[F_];
    so[c] = d_o[row * F_ + c];
    __syncthreads();
    float acc = 0.f;
#pragma unroll 8
    for (int k = 0; k < F_; k++) acc += so[k] * q[k * F_ + c];
    d_oq[row * F_ + c] = acc;
}

// ---- g = ELU(oq @ theta)  [1984,256]@[256,15872] ----
#define BM 64
#define BN 128
#define BK 16
__global__ __launch_bounds__(256) void gemmB_kernel(const float* __restrict__ Bmat) {
    __shared__ float As[BK][BM];
    __shared__ float Bs[BK][BN];
    const int bm = blockIdx.y * BM;
    const int bn = blockIdx.x * BN;
    const int t = threadIdx.x;
    const int tx = t & 15, ty = t >> 4;
    float acc[4][8];
#pragma unroll
    for (int i = 0; i < 4; i++)
#pragma unroll
        for (int j = 0; j < 8; j++) acc[i][j] = 0.f;

    for (int k0 = 0; k0 < F_; k0 += BK) {
        {   // A tile: 64x16
            int row = t >> 2;
            int col = (t & 3) << 2;
            float4 v = *reinterpret_cast<const float4*>(d_oq + (size_t)(bm + row) * F_ + k0 + col);
            As[col][row] = v.x; As[col + 1][row] = v.y;
            As[col + 2][row] = v.z; As[col + 3][row] = v.w;
        }
        {   // B tile: 16x128
#pragma unroll
            for (int i = 0; i < 2; i++) {
                int lin = t + i * 256;
                int kr = lin >> 5;
                int n4 = (lin & 31) << 2;
                float4 v = *reinterpret_cast<const float4*>(Bmat + (size_t)(k0 + kr) * NCF + bn + n4);
                *reinterpret_cast<float4*>(&Bs[kr][n4]) = v;
            }
        }
        __syncthreads();
#pragma unroll
        for (int k = 0; k < BK; k++) {
            float a[4], bb[8];
#pragma unroll
            for (int i = 0; i < 4; i++) a[i] = As[k][ty * 4 + i];
#pragma unroll
            for (int j = 0; j < 8; j++) bb[j] = Bs[k][tx * 8 + j];
#pragma unroll
            for (int i = 0; i < 4; i++)
#pragma unroll
                for (int j = 0; j < 8; j++) acc[i][j] += a[i] * bb[j];
        }
        __syncthreads();
    }
#pragma unroll
    for (int i = 0; i < 4; i++) {
        float* cp = d_g + (size_t)(bm + ty * 4 + i) * NCF + bn + tx * 8;
#pragma unroll
        for (int j = 0; j < 8; j++) cp[j] = elu1(acc[i][j]);
    }
}

// ---- L1 normalize over j (in place: g -> z) ----
__global__ __launch_bounds__(256) void norm_kernel() {
    int row = blockIdx.x;           // b*NC+i
    int c = threadIdx.x;
    float* base = d_g + (size_t)row * NCF;
    float s = 0.f;
#pragma unroll 1
    for (int j = 0; j < NC; j++) s += fabsf(base[j * F_ + c]);
    float inv = 1.f / (s + 1e-6f);
#pragma unroll 1
    for (int j = 0; j < NC; j++) base[j * F_ + c] *= inv;
}

// ---- VQ: scores GEMM [64 x 512 x 256] per block + argmin + loss + hist ----
__global__ __launch_bounds__(256) void vq_kernel(const float* __restrict__ cb) {
    __shared__ float As[BK][BM];
    __shared__ float Bs[BK][BN];
    __shared__ unsigned long long best[BM];
    __shared__ float cn[NE];
    __shared__ float red[256];
    const int t = threadIdx.x;
    const int tx = t & 15, ty = t >> 4;
    const int bm = blockIdx.x * BM;

    if (t < BM) best[t] = 0xFFFFFFFFFFFFFFFFULL;
    for (int i = t; i < NE; i += 256) cn[i] = d_cbnorm[i];
    __syncthreads();

    for (int chunk = 0; chunk < NE / BN; chunk++) {
        const int n0 = chunk * BN;
        float acc[4][8];
#pragma unroll
        for (int i = 0; i < 4; i++)
#pragma unroll
            for (int j = 0; j < 8; j++) acc[i][j] = 0.f;

        for (int k0 = 0; k0 < F_; k0 += BK) {
            {
                int row = t >> 2;
                int col = (t & 3) << 2;
                float4 v = *reinterpret_cast<const float4*>(d_g + (size_t)(bm + row) * F_ + k0 + col);
                As[col][row] = v.x; As[col + 1][row] = v.y;
                As[col + 2][row] = v.z; As[col + 3][row] = v.w;
            }
            {
#pragma unroll
                for (int i = 0; i < 2; i++) {
                    int lin = t + i * 256;
                    int kr = lin >> 5;
                    int n4 = (lin & 31) << 2;
                    float4 v = *reinterpret_cast<const float4*>(d_cbT + (size_t)(k0 + kr) * NE + n0 + n4);
                    *reinterpret_cast<float4*>(&Bs[kr][n4]) = v;
                }
            }
            __syncthreads();
#pragma unroll
            for (int k = 0; k < BK; k++) {
                float a[4], bb[8];
#pragma unroll
                for (int i = 0; i < 4; i++) a[i] = As[k][ty * 4 + i];
#pragma unroll
                for (int j = 0; j < 8; j++) bb[j] = Bs[k][tx * 8 + j];
#pragma unroll
                for (int i = 0; i < 4; i++)
#pragma unroll
                    for (int j = 0; j < 8; j++) acc[i][j] += a[i] * bb[j];
            }
            __syncthreads();
        }
        // argmin update: dist = ||c||^2 - 2*score  (||z||^2 constant per row)
#pragma unroll
        for (int i = 0; i < 4; i++) {
            float dmin = 3.402823e38f;
            int kmin = n0 + tx * 8;
#pragma unroll
            for (int j = 0; j < 8; j++) {
                int kg = n0 + tx * 8 + j;
                float dd = cn[kg] - 2.f * acc[i][j];
                if (dd < dmin) { dmin = dd; kmin = kg; }
            }
            unsigned u = __float_as_uint(dmin);
            u = (u & 0x80000000u) ? ~u : (u | 0x80000000u);
            unsigned long long key = ((unsigned long long)u << 32) | (unsigned)kmin;
            atomicMin(&best[ty * 4 + i], key);
        }
        __syncthreads();
    }

    // winner per row: index + per-batch histogram
    if (t < BM) {
        int r = bm + t;
        int k = (int)(best[t] & 0xFFFFFFFFULL);
        d_idx[r] = k;
        int b = r / (NC * NC);
        atomicAdd(&d_histb[b * NE + k], 1);
    }
    __syncthreads();

    // loss: sum (cb[k] - z)^2 over the 64 rows
    {
        int rl = t >> 2;
        int seg = (t & 3) << 6;
        int r = bm + rl;
        int k = (int)(best[rl] & 0xFFFFFFFFULL);
        const float* zr = d_g + (size_t)r * F_ + seg;
        const float* cr = cb + (size_t)k * F_ + seg;
        float ls = 0.f;
#pragma unroll 8
        for (int c = 0; c < 64; c++) { float dd = cr[c] - zr[c]; ls += dd * dd; }
        red[t] = ls;
        __syncthreads();
        for (int s = 128; s > 0; s >>= 1) {
            if (t < s) red[t] += red[t + s];
            __syncthreads();
        }
        if (t == 0) atomicAdd(&d_loss, red[0]);
    }
}

// ---- SE block: squeeze from histogram, MLP, sigmoid; sfac = 1+s ----
__global__ __launch_bounds__(256) void se_kernel(const float* __restrict__ cb,
                                                 const float* __restrict__ w1,
                                                 const float* __restrict__ b1,
                                                 const float* __restrict__ w2,
                                                 const float* __restrict__ b2) {
    int b = blockIdx.x;
    int c = threadIdx.x;
    __shared__ float sraw[F_];
    __shared__ float h[16];
    float acc = 0.f;
#pragma unroll 4
    for (int k = 0; k < NE; k++) {
        int cnt = d_histb[b * NE + k];
        acc += (float)cnt * cb[k * F_ + c];
    }
    sraw[c] = acc * (1.f / (float)(NC * NC));
    __syncthreads();
    if (c < 16) {
        float a = b1[c];
#pragma unroll 8
        for (int i = 0; i < F_; i++) a += sraw[i] * w1[i * 16 + c];
        h[c] = fmaxf(a, 0.f);
    }
    __syncthreads();
    float a2 = b2[c];
#pragma unroll
    for (int r = 0; r < 16; r++) a2 += h[r] * w2[r * F_ + c];
    float sg = 1.f / (1.f + expf(-a2));
    d_sfac[b * F_ + c] = 1.f + sg;
}

// ---- T[b,k] = sum_c elu(cb[k,c] * sfac[b,c]) ----
__global__ __launch_bounds__(256) void ttab_kernel(const float* __restrict__ cb) {
    int k = blockIdx.x;
    int b = blockIdx.y;
    int c = threadIdx.x;
    __shared__ float red[256];
    float v = cb[k * F_ + c] * d_sfac[b * F_ + c];
    red[c] = elu1(v);
    __syncthreads();
    for (int s = 128; s > 0; s >>= 1) {
        if (c < s) red[c] += red[c + s];
        __syncthreads();
    }
    if (c == 0) d_T[b * NE + k] = red[0];
}

// ---- final: u = elu(T[b, idx]); out = u / (sum_j |u| + eps) ----
__global__ __launch_bounds__(64) void final_kernel(float* __restrict__ out, int adj_off) {
    int row = blockIdx.x;           // b*NC + i
    int b = row / NC;
    int j = threadIdx.x;
    __shared__ float u[64];
    __shared__ float red[64];
    float val = 0.f;
    if (j < NC) {
        int k = d_idx[row * NC + j];
        val = elu1(d_T[b * NE + k]);
    }
    u[j] = val;
    red[j] = fabsf(val);
    __syncthreads();
    for (int s = 32; s > 0; s >>= 1) {
        if (j < s) red[j] += red[j + s];
        __syncthreads();
    }
    if (j < NC) out[adj_off + (size_t)row * NC + j] = u[j] / (red[0] + 1e-6f);
}

// ---- scalars: vq_loss and usage (perplexity) ----
__global__ __launch_bounds__(512) void scalars_kernel(float* __restrict__ out) {
    int k = threadIdx.x;
    __shared__ float red[NE];
    int cnt = 0;
    for (int b = 0; b < B_SZ; b++) cnt += d_histb[b * NE + k];
    float pr = (float)cnt * (1.f / (float)ZROWS);
    red[k] = pr * logf(pr + 1e-10f);
    __syncthreads();
    for (int s = 256; s > 0; s >>= 1) {
        if (k < s) red[k] += red[k + s];
        __syncthreads();
    }
    if (k == 0) {
        out[0] = 1.25f * d_loss / (float)GSIZE;
        out[1 + ZROWS] = expf(-red[0]);
    }
}

// ---- codebook passthrough ----
__global__ __launch_bounds__(256) void copycb_kernel(const float* __restrict__ cb,
                                                     float* __restrict__ out) {
    int k = blockIdx.x, c = threadIdx.x;
    out[2 + ZROWS + (size_t)k * F_ + c] = cb[k * F_ + c];
}

extern "C" void kernel_launch(void* const* d_in, const int* in_sizes, int n_in,
                              void* d_out, int out_size) {
    const float* x     = (const float*)d_in[0];
    const float* p     = (const float*)d_in[1];
    const float* bias  = (const float*)d_in[2];
    const float* q     = (const float*)d_in[3];
    const float* theta = (const float*)d_in[4];
    const float* cb    = (const float*)d_in[5];
    const float* w1    = (const float*)d_in[6];
    const float* b1    = (const float*)d_in[7];
    const float* w2    = (const float*)d_in[8];
    const float* b2    = (const float*)d_in[9];
    float* out = (float*)d_out;

    // Tuple-concat layout: [vq_loss(1), adj(123008), usage(1), codebook(131072)].
    // If harness only wants adj, write it at offset 0.
    int full = (out_size >= (1 + ZROWS + 1 + NE * F_)) ? 1 : 0;
    int adj_off = full ? 1 : 0;

    init_kernel<<<1, 512>>>();
    cbprep_kernel<<<NE, 256>>>(cb);
    a1_kernel<<<MROWS, 256>>>(p, x, bias);
    a2_kernel<<<MROWS, 256>>>(q);
    gemmB_kernel<<<dim3(NCF / BN, MROWS / BM), 256>>>(theta);
    norm_kernel<<<MROWS, 256>>>();
    vq_kernel<<<ZROWS / BM, 256>>>(cb);
    se_kernel<<<B_SZ, 256>>>(cb, w1, b1, w2, b2);
    ttab_kernel<<<dim3(NE, B_SZ), 256>>>(cb);
    final_kernel<<<MROWS, 64>>>(out, adj_off);
    if (full) {
        scalars_kernel<<<1, 512>>>(out);
        copycb_kernel<<<NE, 256>>>(cb, out);
    }
}

// round 3
// speedup vs baseline: 1.1562x; 1.1562x over previous
#include <cuda_runtime.h>
#include <math.h>

typedef unsigned long long ull;

#define B_SZ   32
#define NC     62
#define F_     256
#define NE     512
#define NCF    15872          // NC*F_
#define MROWS  1984           // B_SZ*NC
#define ZROWS  123008         // B_SZ*NC*NC
#define GSIZE  31490048       // MROWS*NCF == ZROWS*F_

// ---- scratch (static device globals: no allocation allowed) ----
__device__ float d_o[MROWS * F_];
__device__ float d_oq[MROWS * F_];
__device__ float d_g[GSIZE];          // g, then z in-place
__device__ float d_cbT[F_ * NE];      // codebook transposed [c][k]
__device__ float d_cbnorm[NE];
__device__ int   d_idx[ZROWS];
__device__ int   d_histb[B_SZ * NE];
__device__ float d_sfac[B_SZ * F_];   // 1 + sigmoid(...)
__device__ float d_T[B_SZ * NE];      // lookup: sum_c elu(cb[k,c]*sfac[b,c])
__device__ float d_loss;

__device__ __forceinline__ float elu1(float x) {
    return x > 0.f ? x : (expf(x) - 1.f);
}

// ---- packed f32x2 helpers (FFMA2 path, 2 MACs per issue slot) ----
__device__ __forceinline__ ull pack2(float x) {
    ull r;
    asm("mov.b64 %0, {%1, %1};" : "=l"(r) : "r"(__float_as_uint(x)));
    return r;
}
__device__ __forceinline__ void fma2(ull& d, ull a, ull b) {
    asm("fma.rn.f32x2 %0, %1, %2, %0;" : "+l"(d) : "l"(a), "l"(b));
}
__device__ __forceinline__ float2 unpack2(ull v) {
    float2 f;
    asm("mov.b64 {%0, %1}, %2;" : "=f"(f.x), "=f"(f.y) : "l"(v));
    return f;
}

// ---- zero per-call state ----
__global__ void init_kernel() {
    int t = threadIdx.x;
    for (int i = t; i < B_SZ * NE; i += blockDim.x) d_histb[i] = 0;
    if (t == 0) d_loss = 0.f;
}

// ---- codebook transpose + squared norms ----
__global__ __launch_bounds__(256) void cbprep_kernel(const float* __restrict__ cb) {
    int k = blockIdx.x, c = threadIdx.x;
    float v = cb[k * F_ + c];
    d_cbT[c * NE + k] = v;
    __shared__ float red[256];
    red[c] = v * v;
    __syncthreads();
    for (int s = 128; s > 0; s >>= 1) {
        if (c < s) red[c] += red[c + s];
        __syncthreads();
    }
    if (c == 0) d_cbnorm[k] = red[0];
}

// ---- o = p @ x + bias ----
__global__ __launch_bounds__(256) void a1_kernel(const float* __restrict__ p,
                                                 const float* __restrict__ x,
                                                 const float* __restrict__ bias) {
    int row = blockIdx.x;           // b*NC + i
    int b = row / NC, i = row - b * NC;
    int c = threadIdx.x;
    __shared__ float sp[NC];
    if (c < NC) sp[c] = p[i * NC + c];
    __syncthreads();
    float a0 = bias[i * F_ + c], a1 = 0.f;
    const float* xb = x + (size_t)b * NC * F_ + c;
#pragma unroll 2
    for (int j = 0; j < NC; j += 2) {
        a0 += sp[j] * xb[j * F_];
        a1 += sp[j + 1] * xb[(j + 1) * F_];
    }
    d_o[row * F_ + c] = a0 + a1;
}

// ---- oq = o @ q ----
__global__ __launch_bounds__(256) void a2_kernel(const float* __restrict__ q) {
    int row = blockIdx.x;
    int c = threadIdx.x;
    __shared__ float so[F_];
    so[c] = d_o[row * F_ + c];
    __syncthreads();
    float a0 = 0.f, a1 = 0.f, a2 = 0.f, a3 = 0.f;
#pragma unroll 4
    for (int k = 0; k < F_; k += 4) {
        a0 += so[k] * q[k * F_ + c];
        a1 += so[k + 1] * q[(k + 1) * F_ + c];
        a2 += so[k + 2] * q[(k + 2) * F_ + c];
        a3 += so[k + 3] * q[(k + 3) * F_ + c];
    }
    d_oq[row * F_ + c] = (a0 + a1) + (a2 + a3);
}

// ---- g = ELU(oq @ theta)  [1984,256]@[256,15872] with FFMA2 ----
#define BM 64
#define BN 128
#define BK 16
__global__ __launch_bounds__(256) void gemmB_kernel(const float* __restrict__ Bmat) {
    __shared__ __align__(16) float As[BK][BM];
    __shared__ __align__(16) float Bs[BK][BN];
    const int bm = blockIdx.y * BM;
    const int bn = blockIdx.x * BN;
    const int t = threadIdx.x;
    const int tx = t & 15, ty = t >> 4;
    ull acc[4][4];
#pragma unroll
    for (int i = 0; i < 4; i++)
#pragma unroll
        for (int j = 0; j < 4; j++) acc[i][j] = 0ULL;

    for (int k0 = 0; k0 < F_; k0 += BK) {
        {   // A tile: 64x16 (thread t always loads row t>>2)
            int row = t >> 2;
            int col = (t & 3) << 2;
            float4 v = *reinterpret_cast<const float4*>(d_oq + (size_t)(bm + row) * F_ + k0 + col);
            As[col][row] = v.x; As[col + 1][row] = v.y;
            As[col + 2][row] = v.z; As[col + 3][row] = v.w;
        }
        {   // B tile: 16x128
#pragma unroll
            for (int i = 0; i < 2; i++) {
                int lin = t + i * 256;
                int kr = lin >> 5;
                int n4 = (lin & 31) << 2;
                float4 v = *reinterpret_cast<const float4*>(Bmat + (size_t)(k0 + kr) * NCF + bn + n4);
                *reinterpret_cast<float4*>(&Bs[kr][n4]) = v;
            }
        }
        __syncthreads();
#pragma unroll
        for (int k = 0; k < BK; k++) {
            ull a2v[4];
#pragma unroll
            for (int i = 0; i < 4; i++) a2v[i] = pack2(As[k][ty * 4 + i]);
            const ull* bp = reinterpret_cast<const ull*>(&Bs[k][tx * 8]);
            ull b0 = bp[0], b1 = bp[1], b2 = bp[2], b3 = bp[3];
#pragma unroll
            for (int i = 0; i < 4; i++) {
                fma2(acc[i][0], a2v[i], b0);
                fma2(acc[i][1], a2v[i], b1);
                fma2(acc[i][2], a2v[i], b2);
                fma2(acc[i][3], a2v[i], b3);
            }
        }
        __syncthreads();
    }
#pragma unroll
    for (int i = 0; i < 4; i++) {
        float* cp = d_g + (size_t)(bm + ty * 4 + i) * NCF + bn + tx * 8;
#pragma unroll
        for (int j = 0; j < 4; j++) {
            float2 f = unpack2(acc[i][j]);
            cp[2 * j] = elu1(f.x);
            cp[2 * j + 1] = elu1(f.y);
        }
    }
}

// ---- L1 normalize over j (in place: g -> z) ----
__global__ __launch_bounds__(256) void norm_kernel() {
    int row = blockIdx.x;           // b*NC+i
    int c = threadIdx.x;
    float* base = d_g + (size_t)row * NCF;
    float s = 0.f;
#pragma unroll 1
    for (int j = 0; j < NC; j++) s += fabsf(base[j * F_ + c]);
    float inv = 1.f / (s + 1e-6f);
#pragma unroll 1
    for (int j = 0; j < NC; j++) base[j * F_ + c] *= inv;
}

// ---- VQ: scores GEMM [64 x 512 x 256] per block (FFMA2) + fused argmin/loss/hist ----
__global__ __launch_bounds__(256) void vq_kernel() {
    __shared__ __align__(16) float As[BK][BM];
    __shared__ __align__(16) float Bs[BK][BN];
    __shared__ unsigned long long best[BM];
    __shared__ float sznorm[BM];
    __shared__ float cn[NE];
    __shared__ float red[64];
    const int t = threadIdx.x;
    const int tx = t & 15, ty = t >> 4;
    const int bm = blockIdx.x * BM;

    if (t < BM) { best[t] = 0xFFFFFFFFFFFFFFFFULL; sznorm[t] = 0.f; }
    for (int i = t; i < NE; i += 256) cn[i] = d_cbnorm[i];
    __syncthreads();

    for (int chunk = 0; chunk < NE / BN; chunk++) {
        const int n0 = chunk * BN;
        ull acc[4][4];
#pragma unroll
        for (int i = 0; i < 4; i++)
#pragma unroll
            for (int j = 0; j < 4; j++) acc[i][j] = 0ULL;

        float z2part = 0.f;
        for (int k0 = 0; k0 < F_; k0 += BK) {
            {
                int row = t >> 2;
                int col = (t & 3) << 2;
                float4 v = *reinterpret_cast<const float4*>(d_g + (size_t)(bm + row) * F_ + k0 + col);
                if (chunk == 0)
                    z2part += v.x * v.x + v.y * v.y + v.z * v.z + v.w * v.w;
                As[col][row] = v.x; As[col + 1][row] = v.y;
                As[col + 2][row] = v.z; As[col + 3][row] = v.w;
            }
            {
#pragma unroll
                for (int i = 0; i < 2; i++) {
                    int lin = t + i * 256;
                    int kr = lin >> 5;
                    int n4 = (lin & 31) << 2;
                    float4 v = *reinterpret_cast<const float4*>(d_cbT + (size_t)(k0 + kr) * NE + n0 + n4);
                    *reinterpret_cast<float4*>(&Bs[kr][n4]) = v;
                }
            }
            __syncthreads();
#pragma unroll
            for (int k = 0; k < BK; k++) {
                ull a2v[4];
#pragma unroll
                for (int i = 0; i < 4; i++) a2v[i] = pack2(As[k][ty * 4 + i]);
                const ull* bp = reinterpret_cast<const ull*>(&Bs[k][tx * 8]);
                ull b0 = bp[0], b1 = bp[1], b2 = bp[2], b3 = bp[3];
#pragma unroll
                for (int i = 0; i < 4; i++) {
                    fma2(acc[i][0], a2v[i], b0);
                    fma2(acc[i][1], a2v[i], b1);
                    fma2(acc[i][2], a2v[i], b2);
                    fma2(acc[i][3], a2v[i], b3);
                }
            }
            __syncthreads();
        }
        if (chunk == 0) atomicAdd(&sznorm[t >> 2], z2part);  // ||z||^2 per row (4 partials)

        // argmin update: dist = ||c||^2 - 2*score  (||z||^2 constant per row)
#pragma unroll
        for (int i = 0; i < 4; i++) {
            float dmin = 3.402823e38f;
            int kmin = n0 + tx * 8;
#pragma unroll
            for (int j = 0; j < 4; j++) {
                float2 f = unpack2(acc[i][j]);
                int kg = n0 + tx * 8 + 2 * j;
                float d0 = cn[kg] - 2.f * f.x;
                float d1 = cn[kg + 1] - 2.f * f.y;
                if (d0 < dmin) { dmin = d0; kmin = kg; }
                if (d1 < dmin) { dmin = d1; kmin = kg + 1; }
            }
            unsigned u = __float_as_uint(dmin);
            u = (u & 0x80000000u) ? ~u : (u | 0x80000000u);
            unsigned long long key = ((unsigned long long)u << 32) | (unsigned)kmin;
            atomicMin(&best[ty * 4 + i], key);
        }
        __syncthreads();
    }

    // winners: index + per-batch histogram + loss = dmin + ||z||^2
    if (t < BM) {
        int r = bm + t;
        unsigned long long key = best[t];
        int k = (int)(key & 0xFFFFFFFFULL);
        d_idx[r] = k;
        int b = r / (NC * NC);
        atomicAdd(&d_histb[b * NE + k], 1);
        unsigned uu = (unsigned)(key >> 32);
        unsigned orig = (uu & 0x80000000u) ? (uu & 0x7FFFFFFFu) : ~uu;
        float dmin = __uint_as_float(orig);
        red[t] = dmin + sznorm[t];
    }
    __syncthreads();
    if (t < 32) {
        float ls = red[t] + red[t + 32];
#pragma unroll
        for (int s = 16; s > 0; s >>= 1)
            ls += __shfl_xor_sync(0xFFFFFFFFu, ls, s);
        if (t == 0) atomicAdd(&d_loss, ls);
    }
}

// ---- SE block: squeeze from histogram, MLP, sigmoid; sfac = 1+s ----
__global__ __launch_bounds__(256) void se_kernel(const float* __restrict__ cb,
                                                 const float* __restrict__ w1,
                                                 const float* __restrict__ b1,
                                                 const float* __restrict__ w2,
                                                 const float* __restrict__ b2) {
    int b = blockIdx.x;
    int c = threadIdx.x;
    __shared__ float sraw[F_];
    __shared__ float h[16];
    float acc = 0.f;
#pragma unroll 4
    for (int k = 0; k < NE; k++) {
        int cnt = d_histb[b * NE + k];
        acc += (float)cnt * cb[k * F_ + c];
    }
    sraw[c] = acc * (1.f / (float)(NC * NC));
    __syncthreads();
    if (c < 16) {
        float a = b1[c];
#pragma unroll 8
        for (int i = 0; i < F_; i++) a += sraw[i] * w1[i * 16 + c];
        h[c] = fmaxf(a, 0.f);
    }
    __syncthreads();
    float a2 = b2[c];
#pragma unroll
    for (int r = 0; r < 16; r++) a2 += h[r] * w2[r * F_ + c];
    float sg = 1.f / (1.f + expf(-a2));
    d_sfac[b * F_ + c] = 1.f + sg;
}

// ---- T[b,k] = sum_c elu(cb[k,c] * sfac[b,c]) ----
__global__ __launch_bounds__(256) void ttab_kernel(const float* __restrict__ cb) {
    int k = blockIdx.x;
    int b = blockIdx.y;
    int c = threadIdx.x;
    __shared__ float red[256];
    float v = cb[k * F_ + c] * d_sfac[b * F_ + c];
    red[c] = elu1(v);
    __syncthreads();
    for (int s = 128; s > 0; s >>= 1) {
        if (c < s) red[c] += red[c + s];
        __syncthreads();
    }
    if (c == 0) d_T[b * NE + k] = red[0];
}

// ---- final: u = elu(T[b, idx]); out = u / (sum_j |u| + eps) ----
__global__ __launch_bounds__(64) void final_kernel(float* __restrict__ out, int adj_off) {
    int row = blockIdx.x;           // b*NC + i
    int b = row / NC;
    int j = threadIdx.x;
    __shared__ float u[64];
    __shared__ float red[64];
    float val = 0.f;
    if (j < NC) {
        int k = d_idx[row * NC + j];
        val = elu1(d_T[b * NE + k]);
    }
    u[j] = val;
    red[j] = fabsf(val);
    __syncthreads();
    for (int s = 32; s > 0; s >>= 1) {
        if (j < s) red[j] += red[j + s];
        __syncthreads();
    }
    if (j < NC) out[adj_off + (size_t)row * NC + j] = u[j] / (red[0] + 1e-6f);
}

// ---- scalars: vq_loss and usage (perplexity) ----
__global__ __launch_bounds__(512) void scalars_kernel(float* __restrict__ out) {
    int k = threadIdx.x;
    __shared__ float red[NE];
    int cnt = 0;
    for (int b = 0; b < B_SZ; b++) cnt += d_histb[b * NE + k];
    float pr = (float)cnt * (1.f / (float)ZROWS);
    red[k] = pr * logf(pr + 1e-10f);
    __syncthreads();
    for (int s = 256; s > 0; s >>= 1) {
        if (k < s) red[k] += red[k + s];
        __syncthreads();
    }
    if (k == 0) {
        out[0] = 1.25f * d_loss / (float)GSIZE;
        out[1 + ZROWS] = expf(-red[0]);
    }
}

// ---- codebook passthrough ----
__global__ __launch_bounds__(256) void copycb_kernel(const float* __restrict__ cb,
                                                     float* __restrict__ out) {
    int k = blockIdx.x, c = threadIdx.x;
    out[2 + ZROWS + (size_t)k * F_ + c] = cb[k * F_ + c];
}

extern "C" void kernel_launch(void* const* d_in, const int* in_sizes, int n_in,
                              void* d_out, int out_size) {
    const float* x     = (const float*)d_in[0];
    const float* p     = (const float*)d_in[1];
    const float* bias  = (const float*)d_in[2];
    const float* q     = (const float*)d_in[3];
    const float* theta = (const float*)d_in[4];
    const float* cb    = (const float*)d_in[5];
    const float* w1    = (const float*)d_in[6];
    const float* b1    = (const float*)d_in[7];
    const float* w2    = (const float*)d_in[8];
    const float* b2    = (const float*)d_in[9];
    float* out = (float*)d_out;

    // Tuple-concat layout: [vq_loss(1), adj(123008), usage(1), codebook(131072)].
    int full = (out_size >= (1 + ZROWS + 1 + NE * F_)) ? 1 : 0;
    int adj_off = full ? 1 : 0;

    init_kernel<<<1, 512>>>();
    cbprep_kernel<<<NE, 256>>>(cb);
    a1_kernel<<<MROWS, 256>>>(p, x, bias);
    a2_kernel<<<MROWS, 256>>>(q);
    gemmB_kernel<<<dim3(NCF / BN, MROWS / BM), 256>>>(theta);
    norm_kernel<<<MROWS, 256>>>();
    vq_kernel<<<ZROWS / BM, 256>>>();
    se_kernel<<<B_SZ, 256>>>(cb, w1, b1, w2, b2);
    ttab_kernel<<<dim3(NE, B_SZ), 256>>>(cb);
    final_kernel<<<MROWS, 64>>>(out, adj_off);
    if (full) {
        scalars_kernel<<<1, 512>>>(out);
        copycb_kernel<<<NE, 256>>>(cb, out);
    }
}

// round 6
// speedup vs baseline: 1.8893x; 1.6341x over previous
#include <cuda_runtime.h>
#include <math.h>

typedef unsigned long long ull;

#define B_SZ   32
#define NC     62
#define F_     256
#define NE     512
#define NCF    15872          // NC*F_
#define MROWS  1984           // B_SZ*NC
#define ZROWS  123008         // B_SZ*NC*NC
#define GSIZE  31490048       // MROWS*NCF == ZROWS*F_

#define BM 64
#define BN 256
#define BK 16

// ---- scratch (static device globals: no allocation allowed) ----
__device__ float d_o[MROWS * F_];
__device__ float d_oq[MROWS * F_];
__device__ float d_g[GSIZE];          // unnormalized ELU(oq@theta)
__device__ float d_inv[MROWS * F_];   // 1/(sum_j |g| + eps) per (b,i,c)
__device__ float d_cbT[F_ * NE];      // codebook transposed [c][k]
__device__ float d_cbnorm[NE];
__device__ int   d_idx[ZROWS];
__device__ int   d_histb[B_SZ * NE];
__device__ float d_sfac[B_SZ * F_];
__device__ float d_T[B_SZ * NE];
__device__ float d_loss;

__device__ __forceinline__ float elu1(float x) {
    return x > 0.f ? x : (expf(x) - 1.f);
}

// ---- packed f32x2 helpers ----
__device__ __forceinline__ ull pack2(float x) {
    ull r;
    asm("mov.b64 %0, {%1, %1};" : "=l"(r) : "r"(__float_as_uint(x)));
    return r;
}
__device__ __forceinline__ void fma2(ull& d, ull a, ull b) {
    asm("fma.rn.f32x2 %0, %1, %2, %0;" : "+l"(d) : "l"(a), "l"(b));
}
__device__ __forceinline__ float2 unpack2(ull v) {
    float2 f;
    asm("mov.b64 {%0, %1}, %2;" : "=f"(f.x), "=f"(f.y) : "l"(v));
    return f;
}

// ---- cp.async helpers ----
__device__ __forceinline__ void cp_async16(void* smem, const void* gmem) {
    unsigned saddr = (unsigned)__cvta_generic_to_shared(smem);
    asm volatile("cp.async.ca.shared.global [%0], [%1], 16;" :: "r"(saddr), "l"(gmem));
}
__device__ __forceinline__ void cp_commit() {
    asm volatile("cp.async.commit_group;");
}
__device__ __forceinline__ void cp_wait1() {
    asm volatile("cp.async.wait_group 1;");
}
__device__ __forceinline__ void cp_wait0() {
    asm volatile("cp.async.wait_group 0;");
}

// ---- zero per-call state ----
__global__ void init_kernel() {
    int t = threadIdx.x;
    for (int i = t; i < B_SZ * NE; i += blockDim.x) d_histb[i] = 0;
    if (t == 0) d_loss = 0.f;
}

// ---- codebook transpose + squared norms ----
__global__ __launch_bounds__(256) void cbprep_kernel(const float* __restrict__ cb) {
    int k = blockIdx.x, c = threadIdx.x;
    float v = cb[k * F_ + c];
    d_cbT[c * NE + k] = v;
    __shared__ float red[256];
    red[c] = v * v;
    __syncthreads();
    for (int s = 128; s > 0; s >>= 1) {
        if (c < s) red[c] += red[c + s];
        __syncthreads();
    }
    if (c == 0) d_cbnorm[k] = red[0];
}

// ---- o = p @ x + bias ----
__global__ __launch_bounds__(256) void a1_kernel(const float* __restrict__ p,
                                                 const float* __restrict__ x,
                                                 const float* __restrict__ bias) {
    int row = blockIdx.x;           // b*NC + i
    int b = row / NC, i = row - b * NC;
    int c = threadIdx.x;
    __shared__ float sp[NC];
    if (c < NC) sp[c] = p[i * NC + c];
    __syncthreads();
    float a0 = bias[i * F_ + c], a1 = 0.f;
    const float* xb = x + (size_t)b * NC * F_ + c;
#pragma unroll 2
    for (int j = 0; j < NC; j += 2) {
        a0 += sp[j] * xb[j * F_];
        a1 += sp[j + 1] * xb[(j + 1) * F_];
    }
    d_o[row * F_ + c] = a0 + a1;
}

// ---- oq = o @ q : 4 rows per block sharing q loads ----
__global__ __launch_bounds__(256) void a2_kernel(const float* __restrict__ q) {
    int row0 = blockIdx.x * 4;
    int c = threadIdx.x;
    __shared__ float so[4][F_];
    for (int i = c; i < 4 * F_; i += 256)
        so[i >> 8][i & 255] = d_o[(row0 + (i >> 8)) * F_ + (i & 255)];
    __syncthreads();
    float a0 = 0.f, a1 = 0.f, a2 = 0.f, a3 = 0.f;
#pragma unroll 4
    for (int k = 0; k < F_; k++) {
        float qv = q[k * F_ + c];
        a0 += so[0][k] * qv;
        a1 += so[1][k] * qv;
        a2 += so[2][k] * qv;
        a3 += so[3][k] * qv;
    }
    d_oq[(row0 + 0) * F_ + c] = a0;
    d_oq[(row0 + 1) * F_ + c] = a1;
    d_oq[(row0 + 2) * F_ + c] = a2;
    d_oq[(row0 + 3) * F_ + c] = a3;
}

// ---- g = ELU(oq @ theta)  [1984,256]@[256,15872]  pipelined FFMA2 ----
__global__ __launch_bounds__(256) void gemmB_kernel(const float* __restrict__ Bmat) {
    __shared__ __align__(16) float As[2][BK][68];
    __shared__ __align__(16) float Bs[2][BK][BN];
    const int t = threadIdx.x;
    const int bm = blockIdx.y * BM;
    const int bn = blockIdx.x * BN;
    const int tx = t & 31, ty = t >> 5;
    const int arow = t >> 2, acol = (t & 3) << 2;

    ull acc[4][8];
#pragma unroll
    for (int p = 0; p < 4; p++)
#pragma unroll
        for (int j = 0; j < 8; j++) acc[p][j] = 0ULL;

    const float* aSrc = d_oq + (size_t)(bm + arow) * F_;
    // preload tile 0
    float4 aReg = *reinterpret_cast<const float4*>(aSrc + acol);
#pragma unroll
    for (int i = 0; i < 4; i++) {
        int qd = t + i * 256;
        int kr = qd >> 6, n4 = (qd & 63) << 2;
        cp_async16(&Bs[0][kr][n4], Bmat + (size_t)kr * NCF + bn + n4);
    }
    cp_commit();
    As[0][acol + 0][arow] = aReg.x;
    As[0][acol + 1][arow] = aReg.y;
    As[0][acol + 2][arow] = aReg.z;
    As[0][acol + 3][arow] = aReg.w;

    const int NT = F_ / BK;  // 16
    for (int kt = 0; kt < NT; kt++) {
        const int cur = kt & 1, nxt = cur ^ 1;
        if (kt + 1 < NT) {
            aReg = *reinterpret_cast<const float4*>(aSrc + (kt + 1) * BK + acol);
#pragma unroll
            for (int i = 0; i < 4; i++) {
                int qd = t + i * 256;
                int kr = qd >> 6, n4 = (qd & 63) << 2;
                cp_async16(&Bs[nxt][kr][n4], Bmat + (size_t)((kt + 1) * BK + kr) * NCF + bn + n4);
            }
            cp_commit();
            cp_wait1();
        } else {
            cp_wait0();
        }
        __syncthreads();
#pragma unroll
        for (int k = 0; k < BK; k++) {
            ull a[4];
            const ull* ap = reinterpret_cast<const ull*>(&As[cur][k][ty * 8]);
            a[0] = ap[0]; a[1] = ap[1]; a[2] = ap[2]; a[3] = ap[3];
            float4 f0 = *reinterpret_cast<const float4*>(&Bs[cur][k][tx * 8]);
            float4 f1 = *reinterpret_cast<const float4*>(&Bs[cur][k][tx * 8 + 4]);
            ull b[8];
            b[0] = pack2(f0.x); b[1] = pack2(f0.y); b[2] = pack2(f0.z); b[3] = pack2(f0.w);
            b[4] = pack2(f1.x); b[5] = pack2(f1.y); b[6] = pack2(f1.z); b[7] = pack2(f1.w);
#pragma unroll
            for (int p = 0; p < 4; p++)
#pragma unroll
                for (int j = 0; j < 8; j++) fma2(acc[p][j], a[p], b[j]);
        }
        __syncthreads();
        if (kt + 1 < NT) {
            As[nxt][acol + 0][arow] = aReg.x;
            As[nxt][acol + 1][arow] = aReg.y;
            As[nxt][acol + 2][arow] = aReg.z;
            As[nxt][acol + 3][arow] = aReg.w;
        }
    }

    // epilogue: rows bm+ty*8+2p(+1), cols bn+tx*8..+7
#pragma unroll
    for (int p = 0; p < 4; p++) {
        float r0[8], r1[8];
#pragma unroll
        for (int j = 0; j < 8; j++) {
            float2 f = unpack2(acc[p][j]);
            r0[j] = elu1(f.x);
            r1[j] = elu1(f.y);
        }
        float* c0 = d_g + (size_t)(bm + ty * 8 + 2 * p) * NCF + bn + tx * 8;
        float* c1 = c0 + NCF;
        *reinterpret_cast<float4*>(c0) = make_float4(r0[0], r0[1], r0[2], r0[3]);
        *reinterpret_cast<float4*>(c0 + 4) = make_float4(r0[4], r0[5], r0[6], r0[7]);
        *reinterpret_cast<float4*>(c1) = make_float4(r1[0], r1[1], r1[2], r1[3]);
        *reinterpret_cast<float4*>(c1 + 4) = make_float4(r1[4], r1[5], r1[6], r1[7]);
    }
}

// ---- inv = 1/(sum_j |g| + eps) per (b,i,c) ----
__global__ __launch_bounds__(256) void sumabs_kernel() {
    int row = blockIdx.x;           // b*NC+i
    int c = threadIdx.x;
    const float* base = d_g + (size_t)row * NCF + c;
    float s0 = 0.f, s1 = 0.f;
#pragma unroll 2
    for (int j = 0; j < NC; j += 2) {
        s0 += fabsf(base[j * F_]);
        s1 += fabsf(base[(j + 1) * F_]);
    }
    d_inv[row * F_ + c] = 1.f / (s0 + s1 + 1e-6f);
}

// ---- VQ: [64 x 512 x 256] scores per block, pipelined FFMA2, fused argmin/loss/hist ----
__global__ __launch_bounds__(256) void vq_kernel() {
    __shared__ __align__(16) float As[2][BK][68];
    __shared__ __align__(16) float Bs[2][BK][BN];
    __shared__ float cn[NE];
    __shared__ unsigned long long best[BM];
    __shared__ float sznorm[BM];
    __shared__ float red[64];
    const int t = threadIdx.x;
    const int bm = blockIdx.x * BM;
    const int tx = t & 31, ty = t >> 5;
    const int arow = t >> 2, acol = (t & 3) << 2;

    if (t < BM) { best[t] = 0xFFFFFFFFFFFFFFFFULL; sznorm[t] = 0.f; }
    for (int i = t; i < NE; i += 256) cn[i] = d_cbnorm[i];

    ull acc[4][8];
#pragma unroll
    for (int p = 0; p < 4; p++)
#pragma unroll
        for (int j = 0; j < 8; j++) acc[p][j] = 0ULL;

    const float* aSrc = d_g + (size_t)(bm + arow) * F_;
    const float* invp = d_inv + (size_t)((bm + arow) / NC) * F_;
    float z2acc = 0.f;

    // preload tile 0 (A tile idx 0, B chunk 0 tile 0)
    float4 aReg = *reinterpret_cast<const float4*>(aSrc + acol);
    {
        float4 iv = *reinterpret_cast<const float4*>(invp + acol);
        aReg.x *= iv.x; aReg.y *= iv.y; aReg.z *= iv.z; aReg.w *= iv.w;
        z2acc += aReg.x * aReg.x + aReg.y * aReg.y + aReg.z * aReg.z + aReg.w * aReg.w;
    }
#pragma unroll
    for (int i = 0; i < 4; i++) {
        int qd = t + i * 256;
        int kr = qd >> 6, n4 = (qd & 63) << 2;
        cp_async16(&Bs[0][kr][n4], d_cbT + (size_t)kr * NE + n4);
    }
    cp_commit();
    As[0][acol + 0][arow] = aReg.x;
    As[0][acol + 1][arow] = aReg.y;
    As[0][acol + 2][arow] = aReg.z;
    As[0][acol + 3][arow] = aReg.w;

    const int NT = 32;  // 2 chunks x 16 k-tiles
    for (int kt = 0; kt < NT; kt++) {
        const int cur = kt & 1, nxt = cur ^ 1;
        if (kt + 1 < NT) {
            const int tk = (kt + 1) & 15;          // A tile index
            const int nchunk = (kt + 1) >> 4;      // B chunk
            aReg = *reinterpret_cast<const float4*>(aSrc + tk * BK + acol);
            float4 iv = *reinterpret_cast<const float4*>(invp + tk * BK + acol);
            aReg.x *= iv.x; aReg.y *= iv.y; aReg.z *= iv.z; aReg.w *= iv.w;
            if (kt + 1 < 16)
                z2acc += aReg.x * aReg.x + aReg.y * aReg.y + aReg.z * aReg.z + aReg.w * aReg.w;
#pragma unroll
            for (int i = 0; i < 4; i++) {
                int qd = t + i * 256;
                int kr = qd >> 6, n4 = (qd & 63) << 2;
                cp_async16(&Bs[nxt][kr][n4],
                           d_cbT + (size_t)(tk * BK + kr) * NE + (nchunk << 8) + n4);
            }
            cp_commit();
            cp_wait1();
        } else {
            cp_wait0();
        }
        __syncthreads();
#pragma unroll
        for (int k = 0; k < BK; k++) {
            ull a[4];
            const ull* ap = reinterpret_cast<const ull*>(&As[cur][k][ty * 8]);
            a[0] = ap[0]; a[1] = ap[1]; a[2] = ap[2]; a[3] = ap[3];
            float4 f0 = *reinterpret_cast<const float4*>(&Bs[cur][k][tx * 8]);
            float4 f1 = *reinterpret_cast<const float4*>(&Bs[cur][k][tx * 8 + 4]);
            ull b[8];
            b[0] = pack2(f0.x); b[1] = pack2(f0.y); b[2] = pack2(f0.z); b[3] = pack2(f0.w);
            b[4] = pack2(f1.x); b[5] = pack2(f1.y); b[6] = pack2(f1.z); b[7] = pack2(f1.w);
#pragma unroll
            for (int p = 0; p < 4; p++)
#pragma unroll
                for (int j = 0; j < 8; j++) fma2(acc[p][j], a[p], b[j]);
        }
        // end of chunk: fold argmin, reset acc
        if ((kt & 15) == 15) {
            const int n0 = (kt >> 4) << 8;
#pragma unroll
            for (int p = 0; p < 4; p++) {
                float dmin0 = 3.402823e38f, dmin1 = 3.402823e38f;
                int k0i = 0, k1i = 0;
#pragma unroll
                for (int j = 0; j < 8; j++) {
                    int kg = n0 + tx * 8 + j;
                    float cnv = cn[kg];
                    float2 f = unpack2(acc[p][j]);
                    float d0 = cnv - 2.f * f.x;
                    float d1 = cnv - 2.f * f.y;
                    if (d0 < dmin0) { dmin0 = d0; k0i = kg; }
                    if (d1 < dmin1) { dmin1 = d1; k1i = kg; }
                    acc[p][j] = 0ULL;
                }
                unsigned u0 = __float_as_uint(dmin0);
                u0 = (u0 & 0x80000000u) ? ~u0 : (u0 | 0x80000000u);
                atomicMin(&best[ty * 8 + 2 * p],
                          ((unsigned long long)u0 << 32) | (unsigned)k0i);
                unsigned u1 = __float_as_uint(dmin1);
                u1 = (u1 & 0x80000000u) ? ~u1 : (u1 | 0x80000000u);
                atomicMin(&best[ty * 8 + 2 * p + 1],
                          ((unsigned long long)u1 << 32) | (unsigned)k1i);
            }
        }
        __syncthreads();
        if (kt + 1 < NT) {
            As[nxt][acol + 0][arow] = aReg.x;
            As[nxt][acol + 1][arow] = aReg.y;
            As[nxt][acol + 2][arow] = aReg.z;
            As[nxt][acol + 3][arow] = aReg.w;
        }
    }

    atomicAdd(&sznorm[arow], z2acc);   // ||z||^2 per row (4 partials each)
    __syncthreads();

    // winners: index + per-batch histogram + loss = dmin + ||z||^2
    if (t < BM) {
        int r = bm + t;
        unsigned long long key = best[t];
        int k = (int)(key & 0xFFFFFFFFULL);
        d_idx[r] = k;
        int b = r / (NC * NC);
        atomicAdd(&d_histb[b * NE + k], 1);
        unsigned uu = (unsigned)(key >> 32);
        unsigned orig = (uu & 0x80000000u) ? (uu & 0x7FFFFFFFu) : ~uu;
        red[t] = __uint_as_float(orig) + sznorm[t];
    }
    __syncthreads();
    if (t < 32) {
        float ls = red[t] + red[t + 32];
#pragma unroll
        for (int s = 16; s > 0; s >>= 1)
            ls += __shfl_xor_sync(0xFFFFFFFFu, ls, s);
        if (t == 0) atomicAdd(&d_loss, ls);
    }
}

// ---- SE block: squeeze from histogram, MLP, sigmoid; sfac = 1+s ----
__global__ __launch_bounds__(256) void se_kernel(const float* __restrict__ cb,
                                                 const float* __restrict__ w1,
                                                 const float* __restrict__ b1,
                                                 const float* __restrict__ w2,
                                                 const float* __restrict__ b2) {
    int b = blockIdx.x;
    int c = threadIdx.x;
    __shared__ float sraw[F_];
    __shared__ float h[16];
    float acc = 0.f;
#pragma unroll 4
    for (int k = 0; k < NE; k++) {
        int cnt = d_histb[b * NE + k];
        acc += (float)cnt * cb[k * F_ + c];
    }
    sraw[c] = acc * (1.f / (float)(NC * NC));
    __syncthreads();
    if (c < 16) {
        float a = b1[c];
#pragma unroll 8
        for (int i = 0; i < F_; i++) a += sraw[i] * w1[i * 16 + c];
        h[c] = fmaxf(a, 0.f);
    }
    __syncthreads();
    float a2 = b2[c];
#pragma unroll
    for (int r = 0; r < 16; r++) a2 += h[r] * w2[r * F_ + c];
    float sg = 1.f / (1.f + expf(-a2));
    d_sfac[b * F_ + c] = 1.f + sg;
}

// ---- T[b,k] = sum_c elu(cb[k,c] * sfac[b,c]) ----
__global__ __launch_bounds__(256) void ttab_kernel(const float* __restrict__ cb) {
    int k = blockIdx.x;
    int b = blockIdx.y;
    int c = threadIdx.x;
    __shared__ float red[256];
    float v = cb[k * F_ + c] * d_sfac[b * F_ + c];
    red[c] = elu1(v);
    __syncthreads();
    for (int s = 128; s > 0; s >>= 1) {
        if (c < s) red[c] += red[c + s];
        __syncthreads();
    }
    if (c == 0) d_T[b * NE + k] = red[0];
}

// ---- final: u = elu(T[b, idx]); out = u / (sum_j |u| + eps) ----
__global__ __launch_bounds__(64) void final_kernel(float* __restrict__ out, int adj_off) {
    int row = blockIdx.x;           // b*NC + i
    int b = row / NC;
    int j = threadIdx.x;
    __shared__ float u[64];
    __shared__ float red[64];
    float val = 0.f;
    if (j < NC) {
        int k = d_idx[row * NC + j];
        val = elu1(d_T[b * NE + k]);
    }
    u[j] = val;
    red[j] = fabsf(val);
    __syncthreads();
    for (int s = 32; s > 0; s >>= 1) {
        if (j < s) red[j] += red[j + s];
        __syncthreads();
    }
    if (j < NC) out[adj_off + (size_t)row * NC + j] = u[j] / (red[0] + 1e-6f);
}

// ---- scalars ----
__global__ __launch_bounds__(512) void scalars_kernel(float* __restrict__ out) {
    int k = threadIdx.x;
    __shared__ float red[NE];
    int cnt = 0;
    for (int b = 0; b < B_SZ; b++) cnt += d_histb[b * NE + k];
    float pr = (float)cnt * (1.f / (float)ZROWS);
    red[k] = pr * logf(pr + 1e-10f);
    __syncthreads();
    for (int s = 256; s > 0; s >>= 1) {
        if (k < s) red[k] += red[k + s];
        __syncthreads();
    }
    if (k == 0) {
        out[0] = 1.25f * d_loss / (float)GSIZE;
        out[1 + ZROWS] = expf(-red[0]);
    }
}

// ---- codebook passthrough ----
__global__ __launch_bounds__(256) void copycb_kernel(const float* __restrict__ cb,
                                                     float* __restrict__ out) {
    int k = blockIdx.x, c = threadIdx.x;
    out[2 + ZROWS + (size_t)k * F_ + c] = cb[k * F_ + c];
}

extern "C" void kernel_launch(void* const* d_in, const int* in_sizes, int n_in,
                              void* d_out, int out_size) {
    const float* x     = (const float*)d_in[0];
    const float* p     = (const float*)d_in[1];
    const float* bias  = (const float*)d_in[2];
    const float* q     = (const float*)d_in[3];
    const float* theta = (const float*)d_in[4];
    const float* cb    = (const float*)d_in[5];
    const float* w1    = (const float*)d_in[6];
    const float* b1    = (const float*)d_in[7];
    const float* w2    = (const float*)d_in[8];
    const float* b2    = (const float*)d_in[9];
    float* out = (float*)d_out;

    int full = (out_size >= (1 + ZROWS + 1 + NE * F_)) ? 1 : 0;
    int adj_off = full ? 1 : 0;

    init_kernel<<<1, 512>>>();
    cbprep_kernel<<<NE, 256>>>(cb);
    a1_kernel<<<MROWS, 256>>>(p, x, bias);
    a2_kernel<<<MROWS / 4, 256>>>(q);
    gemmB_kernel<<<dim3(NCF / BN, MROWS / BM), 256>>>(theta);
    sumabs_kernel<<<MROWS, 256>>>();
    vq_kernel<<<ZROWS / BM, 256>>>();
    se_kernel<<<B_SZ, 256>>>(cb, w1, b1, w2, b2);
    ttab_kernel<<<dim3(NE, B_SZ), 256>>>(cb);
    final_kernel<<<MROWS, 64>>>(out, adj_off);
    if (full) {
        scalars_kernel<<<1, 512>>>(out);
        copycb_kernel<<<NE, 256>>>(cb, out);
    }
}

// round 12
// speedup vs baseline: 2.0733x; 1.0974x over previous
#include <cuda_runtime.h>
#include <cuda_bf16.h>
#include <math.h>
#include <stdint.h>

typedef unsigned long long ull;

#define B_SZ   32
#define NC     62
#define F_     256
#define NE     512
#define NCF    15872          // NC*F_
#define MROWS  1984           // B_SZ*NC
#define MPAD   2048
#define ZROWS  123008         // B_SZ*NC*NC
#define GSIZE  31490048       // ZROWS*F_
#define KS     768            // split K = 3*F_

// ---- device scratch ----
__device__ __align__(16) float d_o[MROWS * F_];
__device__ __align__(16) float d_oq[MROWS * F_];
__device__ __align__(16) __nv_bfloat16 d_oqs[MPAD * KS];         // [hi|lo|hi]
__device__ __align__(16) __nv_bfloat16 d_thT[(size_t)NCF * KS];  // theta^T split [hi|hi|lo]
__device__ __align__(16) __nv_bfloat16 d_cbs[NE * KS];           // cb split [hi|hi|lo]
__device__ __align__(16) __nv_bfloat16 d_zs[(size_t)ZROWS * KS]; // z split [hi|lo|hi]
__device__ float d_z2[ZROWS];
__device__ float d_cbnorm[NE];
__device__ int   d_idx[ZROWS];
__device__ int   d_histb[B_SZ * NE];
__device__ float d_sfac[B_SZ * F_];
__device__ float d_T[B_SZ * NE];
__device__ float d_loss;

__device__ __forceinline__ float elu1(float x) {
    return x > 0.f ? x : (expf(x) - 1.f);
}

#define SWZ(off) ((off) ^ (((off) >> 3) & 0x70))

__device__ __forceinline__ uint32_t smem_u32(const void* p) {
    return (uint32_t)__cvta_generic_to_shared(p);
}
__device__ __forceinline__ void cp_async16(uint32_t saddr, const void* gmem) {
    asm volatile("cp.async.ca.shared.global [%0], [%1], 16;" :: "r"(saddr), "l"(gmem));
}
__device__ __forceinline__ void cp_commit() { asm volatile("cp.async.commit_group;"); }
__device__ __forceinline__ void cp_wait1()  { asm volatile("cp.async.wait_group 1;"); }
__device__ __forceinline__ void cp_wait0()  { asm volatile("cp.async.wait_group 0;"); }

__device__ __forceinline__ void ldsm4(uint32_t* r, uint32_t addr) {
    asm volatile("ldmatrix.sync.aligned.m8n8.x4.shared.b16 {%0,%1,%2,%3}, [%4];"
                 : "=r"(r[0]), "=r"(r[1]), "=r"(r[2]), "=r"(r[3]) : "r"(addr));
}
__device__ __forceinline__ void mma16816(float* c, const uint32_t* a, const uint32_t* b) {
    asm volatile("mma.sync.aligned.m16n8k16.row.col.f32.bf16.bf16.f32 "
                 "{%0,%1,%2,%3}, {%4,%5,%6,%7}, {%8,%9}, {%0,%1,%2,%3};"
                 : "+f"(c[0]), "+f"(c[1]), "+f"(c[2]), "+f"(c[3])
                 : "r"(a[0]), "r"(a[1]), "r"(a[2]), "r"(a[3]), "r"(b[0]), "r"(b[1]));
}

// ================= small kernels =================
__global__ void init_kernel() {
    int t = threadIdx.x;
    for (int i = t; i < B_SZ * NE; i += blockDim.x) d_histb[i] = 0;
    if (t == 0) d_loss = 0.f;
}

__global__ __launch_bounds__(256) void cbprep_kernel(const float* __restrict__ cb) {
    int k = blockIdx.x, c = threadIdx.x;
    float v = cb[k * F_ + c];
    __nv_bfloat16 h = __float2bfloat16(v);
    __nv_bfloat16 l = __float2bfloat16(v - __bfloat162float(h));
    d_cbs[k * KS + c] = h;
    d_cbs[k * KS + F_ + c] = h;
    d_cbs[k * KS + 2 * F_ + c] = l;
    __shared__ float red[256];
    red[c] = v * v;
    __syncthreads();
    for (int s = 128; s > 0; s >>= 1) {
        if (c < s) red[c] += red[c + s];
        __syncthreads();
    }
    if (c == 0) d_cbnorm[k] = red[0];
}

__global__ __launch_bounds__(256) void a1_kernel(const float* __restrict__ p,
                                                 const float* __restrict__ x,
                                                 const float* __restrict__ bias) {
    int row = blockIdx.x;
    int b = row / NC, i = row - b * NC;
    int c = threadIdx.x;
    __shared__ float sp[NC];
    if (c < NC) sp[c] = p[i * NC + c];
    __syncthreads();
    float a0 = bias[i * F_ + c], a1 = 0.f;
    const float* xb = x + (size_t)b * NC * F_ + c;
#pragma unroll 2
    for (int j = 0; j < NC; j += 2) {
        a0 += sp[j] * xb[j * F_];
        a1 += sp[j + 1] * xb[(j + 1) * F_];
    }
    d_o[row * F_ + c] = a0 + a1;
}

__global__ __launch_bounds__(256) void a2_kernel(const float* __restrict__ q) {
    int row0 = blockIdx.x * 4;
    int c = threadIdx.x;
    __shared__ float so[4][F_];
    for (int i = c; i < 4 * F_; i += 256)
        so[i >> 8][i & 255] = d_o[(row0 + (i >> 8)) * F_ + (i & 255)];
    __syncthreads();
    float a0 = 0.f, a1 = 0.f, a2 = 0.f, a3 = 0.f;
#pragma unroll 4
    for (int k = 0; k < F_; k++) {
        float qv = q[k * F_ + c];
        a0 += so[0][k] * qv;
        a1 += so[1][k] * qv;
        a2 += so[2][k] * qv;
        a3 += so[3][k] * qv;
    }
    d_oq[(row0 + 0) * F_ + c] = a0;
    d_oq[(row0 + 1) * F_ + c] = a1;
    d_oq[(row0 + 2) * F_ + c] = a2;
    d_oq[(row0 + 3) * F_ + c] = a3;
}

__global__ __launch_bounds__(256) void split_oq_kernel() {
    int r = blockIdx.x, c = threadIdx.x;
    float v = (r < MROWS) ? d_oq[r * F_ + c] : 0.f;
    __nv_bfloat16 h = __float2bfloat16(v);
    __nv_bfloat16 l = __float2bfloat16(v - __bfloat162float(h));
    d_oqs[r * KS + c] = h;
    d_oqs[r * KS + F_ + c] = l;
    d_oqs[r * KS + 2 * F_ + c] = h;
}

__global__ void transTheta_kernel(const float* __restrict__ theta) {
    __shared__ float tile[32][33];
    int n0 = blockIdx.x * 32, k0 = blockIdx.y * 32;
    for (int i = threadIdx.y; i < 32; i += 8)
        tile[i][threadIdx.x] = theta[(size_t)(k0 + i) * NCF + n0 + threadIdx.x];
    __syncthreads();
    for (int i = threadIdx.y; i < 32; i += 8) {
        int n = n0 + i;
        int k = k0 + threadIdx.x;
        float v = tile[threadIdx.x][i];
        __nv_bfloat16 h = __float2bfloat16(v);
        __nv_bfloat16 l = __float2bfloat16(v - __bfloat162float(h));
        d_thT[(size_t)n * KS + k] = h;
        d_thT[(size_t)n * KS + F_ + k] = h;
        d_thT[(size_t)n * KS + 2 * F_ + k] = l;
    }
}

// ================= HMMA GEMM 1: g = ELU(oq @ theta), split bf16 =================
// block 128x128, K=768 in 12 tiles of 64; smem: A 2x16KB @0, B 2x16KB @32768
#define T_SMEM 65536
__global__ __launch_bounds__(256) void gemmB_mma() {
    extern __shared__ __align__(16) char smem[];
    const int t = threadIdx.x;
    const int wid = t >> 5, lane = t & 31;
    const int warpM = wid & 1, warpN = wid >> 1;
    const int bx = blockIdx.x, mt = blockIdx.y;
    const int j = bx >> 1;
    const int c0base = (bx & 1) << 7;
    const uint32_t sbase = smem_u32(smem);

    float acc[4][4][4];
#pragma unroll
    for (int mi = 0; mi < 4; mi++)
#pragma unroll
        for (int ni = 0; ni < 4; ni++)
#pragma unroll
            for (int e = 0; e < 4; e++) acc[mi][ni][e] = 0.f;

    // A ldmatrix lane geometry
    const uint32_t aRowOff = (uint32_t)((warpM * 64 + (lane & 15)) * 128 + (lane >> 4) * 16);
    const uint32_t bRowOff = (uint32_t)((warpN * 32 + ((lane >> 4) << 3) + (lane & 7)) * 128
                                        + ((lane >> 3) & 1) * 16);
    const int ldr = t >> 3, ldc = (t & 7) * 8;          // tile loader: 2 rows per thread... (4 iters)

    // ---- preload tile 0 ----
#pragma unroll
    for (int i = 0; i < 4; i++) {
        int id = t + i * 256;
        int r = id >> 3, ch = id & 7;
        uint32_t off = SWZ((uint32_t)(r * 128 + ch * 16));
        cp_async16(sbase + off, d_oqs + (size_t)(mt * 128 + r) * KS + ch * 8);
        cp_async16(sbase + 32768 + off, d_thT + (size_t)(bx * 128 + r) * KS + ch * 8);
    }
    cp_commit();

    for (int kt = 0; kt < 12; kt++) {
        const int cur = kt & 1, nxt = cur ^ 1;
        if (kt < 11) {
#pragma unroll
            for (int i = 0; i < 4; i++) {
                int id = t + i * 256;
                int r = id >> 3, ch = id & 7;
                uint32_t off = SWZ((uint32_t)(r * 128 + ch * 16)) + nxt * 16384;
                cp_async16(sbase + off,
                           d_oqs + (size_t)(mt * 128 + r) * KS + (kt + 1) * 64 + ch * 8);
                cp_async16(sbase + 32768 + off,
                           d_thT + (size_t)(bx * 128 + r) * KS + (kt + 1) * 64 + ch * 8);
            }
            cp_commit();
            cp_wait1();
        } else {
            cp_wait0();
        }
        __syncthreads();
        const uint32_t sA = sbase + cur * 16384;
        const uint32_t sB = sbase + 32768 + cur * 16384;
#pragma unroll
        for (int kk = 0; kk < 4; kk++) {
            uint32_t a[4][4];
#pragma unroll
            for (int mi = 0; mi < 4; mi++) {
                uint32_t off = aRowOff + (uint32_t)(mi * 16 * 128) + (uint32_t)(kk * 32);
                ldsm4(a[mi], sA + SWZ(off));
            }
            uint32_t b[4][2];
#pragma unroll
            for (int pr = 0; pr < 2; pr++) {
                uint32_t off = bRowOff + (uint32_t)(pr * 16 * 128) + (uint32_t)(kk * 32);
                uint32_t r4[4];
                ldsm4(r4, sB + SWZ(off));
                b[pr * 2][0] = r4[0]; b[pr * 2][1] = r4[1];
                b[pr * 2 + 1][0] = r4[2]; b[pr * 2 + 1][1] = r4[3];
            }
#pragma unroll
            for (int mi = 0; mi < 4; mi++)
#pragma unroll
                for (int ni = 0; ni < 4; ni++)
                    mma16816(acc[mi][ni], a[mi], b[ni]);
        }
        __syncthreads();
    }

    // epilogue: ELU + bf16 split -> d_zs hi/lo
    const int rbase = mt * 128 + warpM * 64;
#pragma unroll
    for (int mi = 0; mi < 4; mi++) {
        int r0 = rbase + mi * 16 + (lane >> 2);
        int r1 = r0 + 8;
#pragma unroll
        for (int half = 0; half < 2; half++) {
            int r = half ? r1 : r0;
            if (r < MROWS) {
                size_t zr = ((size_t)r * NC + j) * KS;
                uint32_t* hiDst = (uint32_t*)(d_zs + zr);
                uint32_t* loDst = (uint32_t*)(d_zs + zr + F_);
#pragma unroll
                for (int ni = 0; ni < 4; ni++) {
                    int c = c0base + warpN * 32 + ni * 8 + 2 * (lane & 3);
                    float v0 = elu1(acc[mi][ni][half * 2]);
                    float v1 = elu1(acc[mi][ni][half * 2 + 1]);
                    __nv_bfloat16 h0 = __float2bfloat16(v0);
                    __nv_bfloat16 h1 = __float2bfloat16(v1);
                    __nv_bfloat16 l0 = __float2bfloat16(v0 - __bfloat162float(h0));
                    __nv_bfloat16 l1 = __float2bfloat16(v1 - __bfloat162float(h1));
                    hiDst[c >> 1] = ((uint32_t)__bfloat16_as_ushort(h1) << 16)
                                  | __bfloat16_as_ushort(h0);
                    loDst[c >> 1] = ((uint32_t)__bfloat16_as_ushort(l1) << 16)
                                  | __bfloat16_as_ushort(l0);
                }
            }
        }
    }
    (void)ldr; (void)ldc;
}

// ================= convert: L1-normalize + resplit + ||z||^2 =================
__global__ __launch_bounds__(256) void convert_kernel() {
    int bi = blockIdx.x;
    int c = threadIdx.x;
    int lane = c & 31;
    __shared__ float z2s[NC];
    if (c < NC) z2s[c] = 0.f;
    __nv_bfloat16* base = d_zs + (size_t)bi * NC * KS;
    float s = 0.f;
#pragma unroll 2
    for (int j = 0; j < NC; j++) {
        float h = __bfloat162float(base[j * KS + c]);
        float l = __bfloat162float(base[j * KS + F_ + c]);
        s += fabsf(h + l);
    }
    float inv = 1.f / (s + 1e-6f);
    __syncthreads();
#pragma unroll 1
    for (int j = 0; j < NC; j++) {
        float h = __bfloat162float(base[j * KS + c]);
        float l = __bfloat162float(base[j * KS + F_ + c]);
        float z = (h + l) * inv;
        float zz = z * z;
#pragma unroll
        for (int sh = 16; sh > 0; sh >>= 1)
            zz += __shfl_xor_sync(0xFFFFFFFFu, zz, sh);
        if (lane == 0) atomicAdd(&z2s[j], zz);
        __nv_bfloat16 zh = __float2bfloat16(z);
        __nv_bfloat16 zl = __float2bfloat16(z - __bfloat162float(zh));
        base[j * KS + c] = zh;
        base[j * KS + F_ + c] = zl;
        base[j * KS + 2 * F_ + c] = zh;
    }
    __syncthreads();
    if (c < NC) d_z2[bi * NC + c] = z2s[c];
}

// ================= HMMA GEMM 2: VQ scores + argmin/loss/hist =================
// block: 128 rows x 512 codes (4 chunks of 128); smem 64KB tiles + best + cn + redw
#define V_SMEM (65536 + 1024 + 2048 + 64)
__global__ __launch_bounds__(256) void vq_mma() {
    extern __shared__ __align__(16) char smem[];
    ull* best = (ull*)(smem + 65536);
    float* cn = (float*)(smem + 65536 + 1024);
    float* redw = (float*)(smem + 65536 + 1024 + 2048);
    const int t = threadIdx.x;
    const int wid = t >> 5, lane = t & 31;
    const int warpM = wid & 1, warpN = wid >> 1;
    const int bm = blockIdx.x * 128;
    const uint32_t sbase = smem_u32(smem);

    if (t < 128) best[t] = 0xFFFFFFFFFFFFFFFFULL;
    for (int i = t; i < NE; i += 256) cn[i] = d_cbnorm[i];

    const uint32_t aRowOff = (uint32_t)((warpM * 64 + (lane & 15)) * 128 + (lane >> 4) * 16);
    const uint32_t bRowOff = (uint32_t)((warpN * 32 + ((lane >> 4) << 3) + (lane & 7)) * 128
                                        + ((lane >> 3) & 1) * 16);

    for (int nc = 0; nc < 4; nc++) {
        float acc[4][4][4];
#pragma unroll
        for (int mi = 0; mi < 4; mi++)
#pragma unroll
            for (int ni = 0; ni < 4; ni++)
#pragma unroll
                for (int e = 0; e < 4; e++) acc[mi][ni][e] = 0.f;

        // preload tile 0
#pragma unroll
        for (int i = 0; i < 4; i++) {
            int id = t + i * 256;
            int r = id >> 3, ch = id & 7;
            uint32_t off = SWZ((uint32_t)(r * 128 + ch * 16));
            cp_async16(sbase + off, d_zs + (size_t)(bm + r) * KS + ch * 8);
            cp_async16(sbase + 32768 + off, d_cbs + (size_t)(nc * 128 + r) * KS + ch * 8);
        }
        cp_commit();

        for (int kt = 0; kt < 12; kt++) {
            const int cur = kt & 1, nxt = cur ^ 1;
            if (kt < 11) {
#pragma unroll
                for (int i = 0; i < 4; i++) {
                    int id = t + i * 256;
                    int r = id >> 3, ch = id & 7;
                    uint32_t off = SWZ((uint32_t)(r * 128 + ch * 16)) + nxt * 16384;
                    cp_async16(sbase + off,
                               d_zs + (size_t)(bm + r) * KS + (kt + 1) * 64 + ch * 8);
                    cp_async16(sbase + 32768 + off,
                               d_cbs + (size_t)(nc * 128 + r) * KS + (kt + 1) * 64 + ch * 8);
                }
                cp_commit();
                cp_wait1();
            } else {
                cp_wait0();
            }
            __syncthreads();
            const uint32_t sA = sbase + cur * 16384;
            const uint32_t sB = sbase + 32768 + cur * 16384;
#pragma unroll
            for (int kk = 0; kk < 4; kk++) {
                uint32_t a[4][4];
#pragma unroll
                for (int mi = 0; mi < 4; mi++) {
                    uint32_t off = aRowOff + (uint32_t)(mi * 16 * 128) + (uint32_t)(kk * 32);
                    ldsm4(a[mi], sA + SWZ(off));
                }
                uint32_t b[4][2];
#pragma unroll
                for (int pr = 0; pr < 2; pr++) {
                    uint32_t off = bRowOff + (uint32_t)(pr * 16 * 128) + (uint32_t)(kk * 32);
                    uint32_t r4[4];
                    ldsm4(r4, sB + SWZ(off));
                    b[pr * 2][0] = r4[0]; b[pr * 2][1] = r4[1];
                    b[pr * 2 + 1][0] = r4[2]; b[pr * 2 + 1][1] = r4[3];
                }
#pragma unroll
                for (int mi = 0; mi < 4; mi++)
#pragma unroll
                    for (int ni = 0; ni < 4; ni++)
                        mma16816(acc[mi][ni], a[mi], b[ni]);
            }
            __syncthreads();
        }

        // fold chunk into best[] (dist = ||cb||^2 - 2*score; ties -> lowest k)
#pragma unroll
        for (int mi = 0; mi < 4; mi++) {
            int rl = warpM * 64 + mi * 16 + (lane >> 2);
            float dmin0 = 3.402823e38f, dmin1 = 3.402823e38f;
            int k0 = 0, k1 = 0;
#pragma unroll
            for (int ni = 0; ni < 4; ni++) {
                int kb = nc * 128 + warpN * 32 + ni * 8 + 2 * (lane & 3);
                float c0 = cn[kb], c1 = cn[kb + 1];
                float d;
                d = c0 - 2.f * acc[mi][ni][0]; if (d < dmin0) { dmin0 = d; k0 = kb; }
                d = c1 - 2.f * acc[mi][ni][1]; if (d < dmin0) { dmin0 = d; k0 = kb + 1; }
                d = c0 - 2.f * acc[mi][ni][2]; if (d < dmin1) { dmin1 = d; k1 = kb; }
                d = c1 - 2.f * acc[mi][ni][3]; if (d < dmin1) { dmin1 = d; k1 = kb + 1; }
            }
            unsigned u0 = __float_as_uint(dmin0);
            u0 = (u0 & 0x80000000u) ? ~u0 : (u0 | 0x80000000u);
            atomicMin(&best[rl], ((ull)u0 << 32) | (unsigned)k0);
            unsigned u1 = __float_as_uint(dmin1);
            u1 = (u1 & 0x80000000u) ? ~u1 : (u1 | 0x80000000u);
            atomicMin(&best[rl + 8], ((ull)u1 << 32) | (unsigned)k1);
        }
        __syncthreads();
    }

    // winners
    float lossv = 0.f;
    if (t < 128) {
        int r = bm + t;
        ull key = best[t];
        int k = (int)(key & 0xFFFFFFFFULL);
        d_idx[r] = k;
        atomicAdd(&d_histb[(r / (NC * NC)) * NE + k], 1);
        unsigned uu = (unsigned)(key >> 32);
        unsigned orig = (uu & 0x80000000u) ? (uu & 0x7FFFFFFFu) : ~uu;
        lossv = __uint_as_float(orig) + d_z2[r];
#pragma unroll
        for (int sh = 16; sh > 0; sh >>= 1)
            lossv += __shfl_xor_sync(0xFFFFFFFFu, lossv, sh);
        if (lane == 0) redw[wid] = lossv;
    }
    __syncthreads();
    if (t == 0) atomicAdd(&d_loss, redw[0] + redw[1] + redw[2] + redw[3]);
}

// ================= tail kernels =================
__global__ __launch_bounds__(256) void se_kernel(const float* __restrict__ cb,
                                                 const float* __restrict__ w1,
                                                 const float* __restrict__ b1,
                                                 const float* __restrict__ w2,
                                                 const float* __restrict__ b2) {
    int b = blockIdx.x;
    int c = threadIdx.x;
    __shared__ float sraw[F_];
    __shared__ float h[16];
    float acc = 0.f;
#pragma unroll 4
    for (int k = 0; k < NE; k++) {
        int cnt = d_histb[b * NE + k];
        acc += (float)cnt * cb[k * F_ + c];
    }
    sraw[c] = acc * (1.f / (float)(NC * NC));
    __syncthreads();
    if (c < 16) {
        float a = b1[c];
#pragma unroll 8
        for (int i = 0; i < F_; i++) a += sraw[i] * w1[i * 16 + c];
        h[c] = fmaxf(a, 0.f);
    }
    __syncthreads();
    float a2 = b2[c];
#pragma unroll
    for (int r = 0; r < 16; r++) a2 += h[r] * w2[r * F_ + c];
    float sg = 1.f / (1.f + expf(-a2));
    d_sfac[b * F_ + c] = 1.f + sg;
}

__global__ __launch_bounds__(256) void ttab_kernel(const float* __restrict__ cb) {
    int k = blockIdx.x;
    int b = blockIdx.y;
    int c = threadIdx.x;
    __shared__ float red[256];
    float v = cb[k * F_ + c] * d_sfac[b * F_ + c];
    red[c] = elu1(v);
    __syncthreads();
    for (int s = 128; s > 0; s >>= 1) {
        if (c < s) red[c] += red[c + s];
        __syncthreads();
    }
    if (c == 0) d_T[b * NE + k] = red[0];
}

__global__ __launch_bounds__(64) void final_kernel(float* __restrict__ out, int adj_off) {
    int row = blockIdx.x;
    int b = row / NC;
    int j = threadIdx.x;
    __shared__ float u[64];
    __shared__ float red[64];
    float val = 0.f;
    if (j < NC) {
        int k = d_idx[row * NC + j];
        val = elu1(d_T[b * NE + k]);
    }
    u[j] = val;
    red[j] = fabsf(val);
    __syncthreads();
    for (int s = 32; s > 0; s >>= 1) {
        if (j < s) red[j] += red[j + s];
        __syncthreads();
    }
    if (j < NC) out[adj_off + (size_t)row * NC + j] = u[j] / (red[0] + 1e-6f);
}

__global__ __launch_bounds__(512) void scalars_kernel(float* __restrict__ out) {
    int k = threadIdx.x;
    __shared__ float red[NE];
    int cnt = 0;
    for (int b = 0; b < B_SZ; b++) cnt += d_histb[b * NE + k];
    float pr = (float)cnt * (1.f / (float)ZROWS);
    red[k] = pr * logf(pr + 1e-10f);
    __syncthreads();
    for (int s = 256; s > 0; s >>= 1) {
        if (k < s) red[k] += red[k + s];
        __syncthreads();
    }
    if (k == 0) {
        out[0] = 1.25f * d_loss / (float)GSIZE;
        out[1 + ZROWS] = expf(-red[0]);
    }
}

__global__ __launch_bounds__(256) void copycb_kernel(const float* __restrict__ cb,
                                                     float* __restrict__ out) {
    int k = blockIdx.x, c = threadIdx.x;
    out[2 + ZROWS + (size_t)k * F_ + c] = cb[k * F_ + c];
}

extern "C" void kernel_launch(void* const* d_in, const int* in_sizes, int n_in,
                              void* d_out, int out_size) {
    const float* x     = (const float*)d_in[0];
    const float* p     = (const float*)d_in[1];
    const float* bias  = (const float*)d_in[2];
    const float* q     = (const float*)d_in[3];
    const float* theta = (const float*)d_in[4];
    const float* cb    = (const float*)d_in[5];
    const float* w1    = (const float*)d_in[6];
    const float* b1    = (const float*)d_in[7];
    const float* w2    = (const float*)d_in[8];
    const float* b2    = (const float*)d_in[9];
    float* out = (float*)d_out;

    int full = (out_size >= (1 + ZROWS + 1 + NE * F_)) ? 1 : 0;
    int adj_off = full ? 1 : 0;

    cudaFuncSetAttribute(gemmB_mma, cudaFuncAttributeMaxDynamicSharedMemorySize, T_SMEM);
    cudaFuncSetAttribute(vq_mma, cudaFuncAttributeMaxDynamicSharedMemorySize, V_SMEM);

    init_kernel<<<1, 512>>>();
    cbprep_kernel<<<NE, 256>>>(cb);
    a1_kernel<<<MROWS, 256>>>(p, x, bias);
    a2_kernel<<<MROWS / 4, 256>>>(q);
    split_oq_kernel<<<MPAD, 256>>>();
    transTheta_kernel<<<dim3(NCF / 32, F_ / 32), dim3(32, 8)>>>(theta);
    gemmB_mma<<<dim3(NCF / 128, MPAD / 128), 256, T_SMEM>>>();
    convert_kernel<<<MROWS, 256>>>();
    vq_mma<<<ZROWS / 128, 256, V_SMEM>>>();
    se_kernel<<<B_SZ, 256>>>(cb, w1, b1, w2, b2);
    ttab_kernel<<<dim3(NE, B_SZ), 256>>>(cb);
    final_kernel<<<MROWS, 64>>>(out, adj_off);
    if (full) {
        scalars_kernel<<<1, 512>>>(out);
        copycb_kernel<<<NE, 256>>>(cb, out);
    }
}

// round 14
// speedup vs baseline: 2.9581x; 1.4268x over previous
#include <cuda_runtime.h>
#include <cuda_bf16.h>
#include <math.h>
#include <stdint.h>

typedef unsigned long long ull;

#define B_SZ   32
#define NC     62
#define F_     256
#define NE     512
#define NCF    15872          // NC*F_
#define MROWS  1984           // B_SZ*NC
#define MPAD   2048
#define ZROWS  123008         // B_SZ*NC*NC
#define GSIZE  31490048       // ZROWS*F_
#define KS     768            // B-side split K = 3*F_
#define KZ     512            // A-side compact split [hi|lo]

// ---- device scratch ----
__device__ __align__(16) float d_o[MROWS * F_];
__device__ __align__(16) float d_oq[MROWS * F_];
__device__ __align__(16) __nv_bfloat16 d_oqs[MPAD * KZ];         // [hi|lo]
__device__ __align__(16) __nv_bfloat16 d_thT[(size_t)NCF * KS];  // theta^T split [hi|hi|lo]
__device__ __align__(16) __nv_bfloat16 d_cbs[NE * KS];           // cb split [hi|hi|lo]
__device__ __align__(16) __nv_bfloat16 d_zs[(size_t)ZROWS * KZ]; // z split [hi|lo]
__device__ float d_z2[ZROWS];
__device__ float d_cbnorm[NE];
__device__ int   d_idx[ZROWS];
__device__ int   d_histb[B_SZ * NE];
__device__ float d_sfac[B_SZ * F_];
__device__ float d_T[B_SZ * NE];
__device__ float d_loss;

__device__ __forceinline__ float elu1(float x) {
    return x > 0.f ? x : (expf(x) - 1.f);
}

#define SWZ(off) ((off) ^ (((off) >> 3) & 0x70))

__device__ __forceinline__ uint32_t smem_u32(const void* p) {
    return (uint32_t)__cvta_generic_to_shared(p);
}
__device__ __forceinline__ void cp_async16(uint32_t saddr, const void* gmem) {
    asm volatile("cp.async.ca.shared.global [%0], [%1], 16;" :: "r"(saddr), "l"(gmem));
}
__device__ __forceinline__ void cp_commit() { asm volatile("cp.async.commit_group;"); }
__device__ __forceinline__ void cp_wait1()  { asm volatile("cp.async.wait_group 1;"); }
__device__ __forceinline__ void cp_wait0()  { asm volatile("cp.async.wait_group 0;"); }

__device__ __forceinline__ void ldsm4(uint32_t* r, uint32_t addr) {
    asm volatile("ldmatrix.sync.aligned.m8n8.x4.shared.b16 {%0,%1,%2,%3}, [%4];"
                 : "=r"(r[0]), "=r"(r[1]), "=r"(r[2]), "=r"(r[3]) : "r"(addr));
}
__device__ __forceinline__ void mma16816(float* c, const uint32_t* a, const uint32_t* b) {
    asm volatile("mma.sync.aligned.m16n8k16.row.col.f32.bf16.bf16.f32 "
                 "{%0,%1,%2,%3}, {%4,%5,%6,%7}, {%8,%9}, {%0,%1,%2,%3};"
                 : "+f"(c[0]), "+f"(c[1]), "+f"(c[2]), "+f"(c[3])
                 : "r"(a[0]), "r"(a[1]), "r"(a[2]), "r"(a[3]), "r"(b[0]), "r"(b[1]));
}

// ================= small kernels =================
__global__ void init_kernel() {
    int t = threadIdx.x;
    for (int i = t; i < B_SZ * NE; i += blockDim.x) d_histb[i] = 0;
    if (t == 0) d_loss = 0.f;
}

__global__ __launch_bounds__(256) void cbprep_kernel(const float* __restrict__ cb) {
    int k = blockIdx.x, c = threadIdx.x;
    float v = cb[k * F_ + c];
    __nv_bfloat16 h = __float2bfloat16(v);
    __nv_bfloat16 l = __float2bfloat16(v - __bfloat162float(h));
    d_cbs[k * KS + c] = h;
    d_cbs[k * KS + F_ + c] = h;
    d_cbs[k * KS + 2 * F_ + c] = l;
    __shared__ float red[256];
    red[c] = v * v;
    __syncthreads();
    for (int s = 128; s > 0; s >>= 1) {
        if (c < s) red[c] += red[c + s];
        __syncthreads();
    }
    if (c == 0) d_cbnorm[k] = red[0];
}

__global__ __launch_bounds__(256) void a1_kernel(const float* __restrict__ p,
                                                 const float* __restrict__ x,
                                                 const float* __restrict__ bias) {
    int row = blockIdx.x;
    int b = row / NC, i = row - b * NC;
    int c = threadIdx.x;
    __shared__ float sp[NC];
    if (c < NC) sp[c] = p[i * NC + c];
    __syncthreads();
    float a0 = bias[i * F_ + c], a1 = 0.f;
    const float* xb = x + (size_t)b * NC * F_ + c;
#pragma unroll 2
    for (int j = 0; j < NC; j += 2) {
        a0 += sp[j] * xb[j * F_];
        a1 += sp[j + 1] * xb[(j + 1) * F_];
    }
    d_o[row * F_ + c] = a0 + a1;
}

// oq = o @ q : 8 rows/block sharing q loads
__global__ __launch_bounds__(256) void a2_kernel(const float* __restrict__ q) {
    int row0 = blockIdx.x * 8;
    int c = threadIdx.x;
    __shared__ float so[8][F_];
    for (int i = c; i < 8 * F_; i += 256)
        so[i >> 8][i & 255] = d_o[(row0 + (i >> 8)) * F_ + (i & 255)];
    __syncthreads();
    float a0 = 0.f, a1 = 0.f, a2 = 0.f, a3 = 0.f;
    float a4 = 0.f, a5 = 0.f, a6 = 0.f, a7 = 0.f;
#pragma unroll 4
    for (int k = 0; k < F_; k++) {
        float qv = q[k * F_ + c];
        a0 += so[0][k] * qv;
        a1 += so[1][k] * qv;
        a2 += so[2][k] * qv;
        a3 += so[3][k] * qv;
        a4 += so[4][k] * qv;
        a5 += so[5][k] * qv;
        a6 += so[6][k] * qv;
        a7 += so[7][k] * qv;
    }
    d_oq[(row0 + 0) * F_ + c] = a0;
    d_oq[(row0 + 1) * F_ + c] = a1;
    d_oq[(row0 + 2) * F_ + c] = a2;
    d_oq[(row0 + 3) * F_ + c] = a3;
    d_oq[(row0 + 4) * F_ + c] = a4;
    d_oq[(row0 + 5) * F_ + c] = a5;
    d_oq[(row0 + 6) * F_ + c] = a6;
    d_oq[(row0 + 7) * F_ + c] = a7;
}

__global__ __launch_bounds__(256) void split_oq_kernel() {
    int r = blockIdx.x, c = threadIdx.x;
    float v = (r < MROWS) ? d_oq[r * F_ + c] : 0.f;
    __nv_bfloat16 h = __float2bfloat16(v);
    __nv_bfloat16 l = __float2bfloat16(v - __bfloat162float(h));
    d_oqs[r * KZ + c] = h;
    d_oqs[r * KZ + F_ + c] = l;
}

__global__ void transTheta_kernel(const float* __restrict__ theta) {
    __shared__ float tile[32][33];
    int n0 = blockIdx.x * 32, k0 = blockIdx.y * 32;
    for (int i = threadIdx.y; i < 32; i += 8)
        tile[i][threadIdx.x] = theta[(size_t)(k0 + i) * NCF + n0 + threadIdx.x];
    __syncthreads();
    for (int i = threadIdx.y; i < 32; i += 8) {
        int n = n0 + i;
        int k = k0 + threadIdx.x;
        float v = tile[threadIdx.x][i];
        __nv_bfloat16 h = __float2bfloat16(v);
        __nv_bfloat16 l = __float2bfloat16(v - __bfloat162float(h));
        d_thT[(size_t)n * KS + k] = h;
        d_thT[(size_t)n * KS + F_ + k] = h;
        d_thT[(size_t)n * KS + 2 * F_ + k] = l;
    }
}

// ================= HMMA GEMM 1: g = ELU(oq @ theta) =================
// block 128x256 (one j per block), 8 warps 2x4, warp tile 64x64, K=768 (A aliased)
#define GB_SMEM 98304
__global__ __launch_bounds__(256) void gemmB_mma() {
    extern __shared__ __align__(16) char smem[];
    const int t = threadIdx.x;
    const int wid = t >> 5, lane = t & 31;
    const int warpM = wid & 1, warpN = wid >> 1;
    const int j = blockIdx.x, mt = blockIdx.y;
    const uint32_t sbase = smem_u32(smem);

    float acc[4][8][4];
#pragma unroll
    for (int mi = 0; mi < 4; mi++)
#pragma unroll
        for (int ni = 0; ni < 8; ni++)
#pragma unroll
            for (int e = 0; e < 4; e++) acc[mi][ni][e] = 0.f;

    const uint32_t aRowOff = (uint32_t)((warpM * 64 + (lane & 15)) * 128 + (lane >> 4) * 16);
    const uint32_t bRowOff = (uint32_t)((warpN * 64 + ((lane >> 4) << 3) + (lane & 7)) * 128
                                        + ((lane >> 3) & 1) * 16);

    // preload kt=0
#pragma unroll
    for (int i = 0; i < 4; i++) {
        int id = t + i * 256;
        int r = id >> 3, ch = id & 7;
        uint32_t off = SWZ((uint32_t)(r * 128 + ch * 16));
        cp_async16(sbase + off, d_oqs + (size_t)(mt * 128 + r) * KZ + ch * 8);
    }
#pragma unroll
    for (int i = 0; i < 8; i++) {
        int id = t + i * 256;
        int r = id >> 3, ch = id & 7;
        uint32_t off = SWZ((uint32_t)(r * 128 + ch * 16));
        cp_async16(sbase + 32768 + off, d_thT + (size_t)(j * 256 + r) * KS + ch * 8);
    }
    cp_commit();

    for (int kt = 0; kt < 12; kt++) {
        const int cur = kt & 1, nxt = cur ^ 1;
        if (kt < 11) {
            const int ka = (kt + 1 < 8) ? (kt + 1) * 64 : (kt + 1 - 8) * 64;  // A alias
#pragma unroll
            for (int i = 0; i < 4; i++) {
                int id = t + i * 256;
                int r = id >> 3, ch = id & 7;
                uint32_t off = SWZ((uint32_t)(r * 128 + ch * 16));
                cp_async16(sbase + nxt * 16384 + off,
                           d_oqs + (size_t)(mt * 128 + r) * KZ + ka + ch * 8);
            }
#pragma unroll
            for (int i = 0; i < 8; i++) {
                int id = t + i * 256;
                int r = id >> 3, ch = id & 7;
                uint32_t off = SWZ((uint32_t)(r * 128 + ch * 16));
                cp_async16(sbase + 32768 + nxt * 32768 + off,
                           d_thT + (size_t)(j * 256 + r) * KS + (kt + 1) * 64 + ch * 8);
            }
            cp_commit();
            cp_wait1();
        } else {
            cp_wait0();
        }
        __syncthreads();
        const uint32_t sA = sbase + cur * 16384;
        const uint32_t sB = sbase + 32768 + cur * 32768;
#pragma unroll
        for (int kk = 0; kk < 4; kk++) {
            uint32_t a[4][4];
#pragma unroll
            for (int mi = 0; mi < 4; mi++)
                ldsm4(a[mi], sA + SWZ(aRowOff + (uint32_t)(mi * 2048) + (uint32_t)(kk * 32)));
            uint32_t b[8][2];
#pragma unroll
            for (int pr = 0; pr < 4; pr++) {
                uint32_t r4[4];
                ldsm4(r4, sB + SWZ(bRowOff + (uint32_t)(pr * 2048) + (uint32_t)(kk * 32)));
                b[pr * 2][0] = r4[0]; b[pr * 2][1] = r4[1];
                b[pr * 2 + 1][0] = r4[2]; b[pr * 2 + 1][1] = r4[3];
            }
#pragma unroll
            for (int mi = 0; mi < 4; mi++)
#pragma unroll
                for (int ni = 0; ni < 8; ni++)
                    mma16816(acc[mi][ni], a[mi], b[ni]);
        }
        __syncthreads();
    }

    // epilogue: ELU + bf16 split -> d_zs [hi|lo]
    const int rbase = mt * 128 + warpM * 64;
#pragma unroll
    for (int mi = 0; mi < 4; mi++) {
#pragma unroll
        for (int half = 0; half < 2; half++) {
            int r = rbase + mi * 16 + (lane >> 2) + half * 8;
            if (r < MROWS) {
                size_t zr = ((size_t)r * NC + j) * KZ;
                uint32_t* hiDst = (uint32_t*)(d_zs + zr);
                uint32_t* loDst = (uint32_t*)(d_zs + zr + F_);
#pragma unroll
                for (int ni = 0; ni < 8; ni++) {
                    int c = warpN * 64 + ni * 8 + 2 * (lane & 3);
                    float v0 = elu1(acc[mi][ni][half * 2]);
                    float v1 = elu1(acc[mi][ni][half * 2 + 1]);
                    __nv_bfloat16 h0 = __float2bfloat16(v0);
                    __nv_bfloat16 h1 = __float2bfloat16(v1);
                    __nv_bfloat16 l0 = __float2bfloat16(v0 - __bfloat162float(h0));
                    __nv_bfloat16 l1 = __float2bfloat16(v1 - __bfloat162float(h1));
                    hiDst[c >> 1] = ((uint32_t)__bfloat16_as_ushort(h1) << 16)
                                  | __bfloat16_as_ushort(h0);
                    loDst[c >> 1] = ((uint32_t)__bfloat16_as_ushort(l1) << 16)
                                  | __bfloat16_as_ushort(l0);
                }
            }
        }
    }
}

// ================= convert: L1-normalize + resplit + ||z||^2 =================
__global__ __launch_bounds__(256) void convert_kernel() {
    int bi = blockIdx.x;
    int c = threadIdx.x;
    int lane = c & 31;
    __shared__ float z2s[NC];
    if (c < NC) z2s[c] = 0.f;
    __nv_bfloat16* base = d_zs + (size_t)bi * NC * KZ;
    float s = 0.f;
#pragma unroll 2
    for (int j = 0; j < NC; j++) {
        float h = __bfloat162float(base[j * KZ + c]);
        float l = __bfloat162float(base[j * KZ + F_ + c]);
        s += fabsf(h + l);
    }
    float inv = 1.f / (s + 1e-6f);
    __syncthreads();
#pragma unroll 1
    for (int j = 0; j < NC; j++) {
        float h = __bfloat162float(base[j * KZ + c]);
        float l = __bfloat162float(base[j * KZ + F_ + c]);
        float z = (h + l) * inv;
        float zz = z * z;
#pragma unroll
        for (int sh = 16; sh > 0; sh >>= 1)
            zz += __shfl_xor_sync(0xFFFFFFFFu, zz, sh);
        if (lane == 0) atomicAdd(&z2s[j], zz);
        __nv_bfloat16 zh = __float2bfloat16(z);
        __nv_bfloat16 zl = __float2bfloat16(z - __bfloat162float(zh));
        base[j * KZ + c] = zh;
        base[j * KZ + F_ + c] = zl;
    }
    __syncthreads();
    if (c < NC) d_z2[bi * NC + c] = z2s[c];
}

// ================= HMMA GEMM 2: VQ scores + argmin/loss/hist =================
// block 128 rows x 512 codes (2 chunks of 256), warp tile 64x64
#define VQ_SMEM (98304 + 1024 + 2048 + 64)
__global__ __launch_bounds__(256) void vq_mma() {
    extern __shared__ __align__(16) char smem[];
    ull* best = (ull*)(smem + 98304);
    float* cn = (float*)(smem + 98304 + 1024);
    float* redw = (float*)(smem + 98304 + 1024 + 2048);
    const int t = threadIdx.x;
    const int wid = t >> 5, lane = t & 31;
    const int warpM = wid & 1, warpN = wid >> 1;
    const int bm = blockIdx.x * 128;
    const uint32_t sbase = smem_u32(smem);

    if (t < 128) best[t] = 0xFFFFFFFFFFFFFFFFULL;
    for (int i = t; i < NE; i += 256) cn[i] = d_cbnorm[i];

    const uint32_t aRowOff = (uint32_t)((warpM * 64 + (lane & 15)) * 128 + (lane >> 4) * 16);
    const uint32_t bRowOff = (uint32_t)((warpN * 64 + ((lane >> 4) << 3) + (lane & 7)) * 128
                                        + ((lane >> 3) & 1) * 16);

    for (int nc = 0; nc < 2; nc++) {
        float acc[4][8][4];
#pragma unroll
        for (int mi = 0; mi < 4; mi++)
#pragma unroll
            for (int ni = 0; ni < 8; ni++)
#pragma unroll
                for (int e = 0; e < 4; e++) acc[mi][ni][e] = 0.f;

        // preload kt=0
#pragma unroll
        for (int i = 0; i < 4; i++) {
            int id = t + i * 256;
            int r = id >> 3, ch = id & 7;
            uint32_t off = SWZ((uint32_t)(r * 128 + ch * 16));
            cp_async16(sbase + off, d_zs + (size_t)(bm + r) * KZ + ch * 8);
        }
#pragma unroll
        for (int i = 0; i < 8; i++) {
            int id = t + i * 256;
            int r = id >> 3, ch = id & 7;
            uint32_t off = SWZ((uint32_t)(r * 128 + ch * 16));
            cp_async16(sbase + 32768 + off, d_cbs + (size_t)(nc * 256 + r) * KS + ch * 8);
        }
        cp_commit();

        for (int kt = 0; kt < 12; kt++) {
            const int cur = kt & 1, nxt = cur ^ 1;
            if (kt < 11) {
                const int ka = (kt + 1 < 8) ? (kt + 1) * 64 : (kt + 1 - 8) * 64;
#pragma unroll
                for (int i = 0; i < 4; i++) {
                    int id = t + i * 256;
                    int r = id >> 3, ch = id & 7;
                    uint32_t off = SWZ((uint32_t)(r * 128 + ch * 16));
                    cp_async16(sbase + nxt * 16384 + off,
                               d_zs + (size_t)(bm + r) * KZ + ka + ch * 8);
                }
#pragma unroll
                for (int i = 0; i < 8; i++) {
                    int id = t + i * 256;
                    int r = id >> 3, ch = id & 7;
                    uint32_t off = SWZ((uint32_t)(r * 128 + ch * 16));
                    cp_async16(sbase + 32768 + nxt * 32768 + off,
                               d_cbs + (size_t)(nc * 256 + r) * KS + (kt + 1) * 64 + ch * 8);
                }
                cp_commit();
                cp_wait1();
            } else {
                cp_wait0();
            }
            __syncthreads();
            const uint32_t sA = sbase + cur * 16384;
            const uint32_t sB = sbase + 32768 + cur * 32768;
#pragma unroll
            for (int kk = 0; kk < 4; kk++) {
                uint32_t a[4][4];
#pragma unroll
                for (int mi = 0; mi < 4; mi++)
                    ldsm4(a[mi], sA + SWZ(aRowOff + (uint32_t)(mi * 2048) + (uint32_t)(kk * 32)));
                uint32_t b[8][2];
#pragma unroll
                for (int pr = 0; pr < 4; pr++) {
                    uint32_t r4[4];
                    ldsm4(r4, sB + SWZ(bRowOff + (uint32_t)(pr * 2048) + (uint32_t)(kk * 32)));
                    b[pr * 2][0] = r4[0]; b[pr * 2][1] = r4[1];
                    b[pr * 2 + 1][0] = r4[2]; b[pr * 2 + 1][1] = r4[3];
                }
#pragma unroll
                for (int mi = 0; mi < 4; mi++)
#pragma unroll
                    for (int ni = 0; ni < 8; ni++)
                        mma16816(acc[mi][ni], a[mi], b[ni]);
            }
            __syncthreads();
        }

        // fold chunk into best[] (dist = ||cb||^2 - 2*score; ties -> lowest k)
#pragma unroll
        for (int mi = 0; mi < 4; mi++) {
            int rl = warpM * 64 + mi * 16 + (lane >> 2);
            float dmin0 = 3.402823e38f, dmin1 = 3.402823e38f;
            int k0 = 0, k1 = 0;
#pragma unroll
            for (int ni = 0; ni < 8; ni++) {
                int kb = nc * 256 + warpN * 64 + ni * 8 + 2 * (lane & 3);
                float c0 = cn[kb], c1 = cn[kb + 1];
                float d;
                d = c0 - 2.f * acc[mi][ni][0]; if (d < dmin0) { dmin0 = d; k0 = kb; }
                d = c1 - 2.f * acc[mi][ni][1]; if (d < dmin0) { dmin0 = d; k0 = kb + 1; }
                d = c0 - 2.f * acc[mi][ni][2]; if (d < dmin1) { dmin1 = d; k1 = kb; }
                d = c1 - 2.f * acc[mi][ni][3]; if (d < dmin1) { dmin1 = d; k1 = kb + 1; }
            }
            unsigned u0 = __float_as_uint(dmin0);
            u0 = (u0 & 0x80000000u) ? ~u0 : (u0 | 0x80000000u);
            atomicMin(&best[rl], ((ull)u0 << 32) | (unsigned)k0);
            unsigned u1 = __float_as_uint(dmin1);
            u1 = (u1 & 0x80000000u) ? ~u1 : (u1 | 0x80000000u);
            atomicMin(&best[rl + 8], ((ull)u1 << 32) | (unsigned)k1);
        }
        __syncthreads();
    }

    // winners
    float lossv = 0.f;
    if (t < 128) {
        int r = bm + t;
        ull key = best[t];
        int k = (int)(key & 0xFFFFFFFFULL);
        d_idx[r] = k;
        atomicAdd(&d_histb[(r / (NC * NC)) * NE + k], 1);
        unsigned uu = (unsigned)(key >> 32);
        unsigned orig = (uu & 0x80000000u) ? (uu & 0x7FFFFFFFu) : ~uu;
        lossv = __uint_as_float(orig) + d_z2[r];
#pragma unroll
        for (int sh = 16; sh > 0; sh >>= 1)
            lossv += __shfl_xor_sync(0xFFFFFFFFu, lossv, sh);
        if (lane == 0) redw[wid] = lossv;
    }
    __syncthreads();
    if (t == 0) atomicAdd(&d_loss, redw[0] + redw[1] + redw[2] + redw[3]);
}

// ================= tail kernels =================
__global__ __launch_bounds__(256) void se_kernel(const float* __restrict__ cb,
                                                 const float* __restrict__ w1,
                                                 const float* __restrict__ b1,
                                                 const float* __restrict__ w2,
                                                 const float* __restrict__ b2) {
    int b = blockIdx.x;
    int c = threadIdx.x;
    __shared__ float sraw[F_];
    __shared__ float h[16];
    float acc = 0.f;
#pragma unroll 4
    for (int k = 0; k < NE; k++) {
        int cnt = d_histb[b * NE + k];
        acc += (float)cnt * cb[k * F_ + c];
    }
    sraw[c] = acc * (1.f / (float)(NC * NC));
    __syncthreads();
    if (c < 16) {
        float a = b1[c];
#pragma unroll 8
        for (int i = 0; i < F_; i++) a += sraw[i] * w1[i * 16 + c];
        h[c] = fmaxf(a, 0.f);
    }
    __syncthreads();
    float a2 = b2[c];
#pragma unroll
    for (int r = 0; r < 16; r++) a2 += h[r] * w2[r * F_ + c];
    float sg = 1.f / (1.f + expf(-a2));
    d_sfac[b * F_ + c] = 1.f + sg;
}

__global__ __launch_bounds__(256) void ttab_kernel(const float* __restrict__ cb) {
    int k = blockIdx.x;
    int b = blockIdx.y;
    int c = threadIdx.x;
    __shared__ float red[256];
    float v = cb[k * F_ + c] * d_sfac[b * F_ + c];
    red[c] = elu1(v);
    __syncthreads();
    for (int s = 128; s > 0; s >>= 1) {
        if (c < s) red[c] += red[c + s];
        __syncthreads();
    }
    if (c == 0) d_T[b * NE + k] = red[0];
}

__global__ __launch_bounds__(64) void final_kernel(float* __restrict__ out, int adj_off) {
    int row = blockIdx.x;
    int b = row / NC;
    int j = threadIdx.x;
    __shared__ float u[64];
    __shared__ float red[64];
    float val = 0.f;
    if (j < NC) {
        int k = d_idx[row * NC + j];
        val = elu1(d_T[b * NE + k]);
    }
    u[j] = val;
    red[j] = fabsf(val);
    __syncthreads();
    for (int s = 32; s > 0; s >>= 1) {
        if (j < s) red[j] += red[j + s];
        __syncthreads();
    }
    if (j < NC) out[adj_off + (size_t)row * NC + j] = u[j] / (red[0] + 1e-6f);
}

__global__ __launch_bounds__(512) void scalars_kernel(float* __restrict__ out) {
    int k = threadIdx.x;
    __shared__ float red[NE];
    int cnt = 0;
    for (int b = 0; b < B_SZ; b++) cnt += d_histb[b * NE + k];
    float pr = (float)cnt * (1.f / (float)ZROWS);
    red[k] = pr * logf(pr + 1e-10f);
    __syncthreads();
    for (int s = 256; s > 0; s >>= 1) {
        if (k < s) red[k] += red[k + s];
        __syncthreads();
    }
    if (k == 0) {
        out[0] = 1.25f * d_loss / (float)GSIZE;
        out[1 + ZROWS] = expf(-red[0]);
    }
}

__global__ __launch_bounds__(256) void copycb_kernel(const float* __restrict__ cb,
                                                     float* __restrict__ out) {
    int k = blockIdx.x, c = threadIdx.x;
    out[2 + ZROWS + (size_t)k * F_ + c] = cb[k * F_ + c];
}

extern "C" void kernel_launch(void* const* d_in, const int* in_sizes, int n_in,
                              void* d_out, int out_size) {
    const float* x     = (const float*)d_in[0];
    const float* p     = (const float*)d_in[1];
    const float* bias  = (const float*)d_in[2];
    const float* q     = (const float*)d_in[3];
    const float* theta = (const float*)d_in[4];
    const float* cb    = (const float*)d_in[5];
    const float* w1    = (const float*)d_in[6];
    const float* b1    = (const float*)d_in[7];
    const float* w2    = (const float*)d_in[8];
    const float* b2    = (const float*)d_in[9];
    float* out = (float*)d_out;

    int full = (out_size >= (1 + ZROWS + 1 + NE * F_)) ? 1 : 0;
    int adj_off = full ? 1 : 0;

    cudaFuncSetAttribute(gemmB_mma, cudaFuncAttributeMaxDynamicSharedMemorySize, GB_SMEM);
    cudaFuncSetAttribute(vq_mma, cudaFuncAttributeMaxDynamicSharedMemorySize, VQ_SMEM);

    init_kernel<<<1, 512>>>();
    cbprep_kernel<<<NE, 256>>>(cb);
    a1_kernel<<<MROWS, 256>>>(p, x, bias);
    a2_kernel<<<MROWS / 8, 256>>>(q);
    split_oq_kernel<<<MPAD, 256>>>();
    transTheta_kernel<<<dim3(NCF / 32, F_ / 32), dim3(32, 8)>>>(theta);
    gemmB_mma<<<dim3(NC, MPAD / 128), 256, GB_SMEM>>>();
    convert_kernel<<<MROWS, 256>>>();
    vq_mma<<<ZROWS / 128, 256, VQ_SMEM>>>();
    se_kernel<<<B_SZ, 256>>>(cb, w1, b1, w2, b2);
    ttab_kernel<<<dim3(NE, B_SZ), 256>>>(cb);
    final_kernel<<<MROWS, 64>>>(out, adj_off);
    if (full) {
        scalars_kernel<<<1, 512>>>(out);
        copycb_kernel<<<NE, 256>>>(cb, out);
    }
}